// round 7
// baseline (speedup 1.0000x reference)
#include <cuda_runtime.h>
#include <cuda_bf16.h>
#include <cstdint>

#define BATCH 2
#define TSEQ 2048
#define CEMB 2048
#define NHEAD 16
#define LDIM 128
#define MROWS (BATCH*TSEQ)
#define QSTR (NHEAD*LDIM)   // 2048

// ---------------------------------------------------------------------------
// Scratch (__device__ globals: allocation-free rule)
// ---------------------------------------------------------------------------
__device__ __nv_bfloat16 g_xh[MROWS*CEMB], g_xl[MROWS*CEMB];   // x split
__device__ __nv_bfloat16 g_qh[MROWS*QSTR], g_ql[MROWS*QSTR];   // q split
__device__ __nv_bfloat16 g_kh[MROWS*LDIM], g_kl[MROWS*LDIM];   // k latent split
__device__ __nv_bfloat16 g_yh[MROWS*QSTR], g_yl[MROWS*QSTR];   // y split
__device__ uint32_t g_wdh[QSTR*(CEMB/2)], g_wdl[QSTR*(CEMB/2)];  // W_d  [N][K/2]
__device__ uint32_t g_wph[CEMB*(QSTR/2)], g_wpl[CEMB*(QSTR/2)];  // W_proj
__device__ uint32_t g_wlh[LDIM*(CEMB/2)], g_wll[LDIM*(CEMB/2)];  // W_lat

// ---------------------------------------------------------------------------
// Helpers
// ---------------------------------------------------------------------------
__device__ __forceinline__ uint32_t smem_u32(const void* p){
    uint32_t a;
    asm("{ .reg .u64 t; cvta.to.shared.u64 t, %1; cvt.u32.u64 %0, t; }"
        : "=r"(a) : "l"(p));
    return a;
}
__device__ __forceinline__ float bfround(float x){
    return __bfloat162float(__float2bfloat16(x));
}
__device__ __forceinline__ uint32_t pack2(float lo, float hi){
    uint32_t r;
    asm("cvt.rn.bf16x2.f32 %0, %1, %2;" : "=r"(r) : "f"(hi), "f"(lo));
    return r;
}

#define CP16(dst_u32, src_ptr) \
    asm volatile("cp.async.cg.shared.global [%0], [%1], 16;" \
                 :: "r"(dst_u32), "l"(src_ptr) : "memory")
#define CP_COMMIT() asm volatile("cp.async.commit_group;" ::: "memory")
#define CP_WAIT(n)  asm volatile("cp.async.wait_group %0;" :: "n"(n) : "memory")

#define LDSM4(R, ADDR)                                                        \
    asm volatile("ldmatrix.sync.aligned.m8n8.x4.shared.b16 {%0,%1,%2,%3}, [%4];" \
        : "=r"((R)[0]), "=r"((R)[1]), "=r"((R)[2]), "=r"((R)[3]) : "r"(ADDR))
#define LDSM4T(R, ADDR)                                                       \
    asm volatile("ldmatrix.sync.aligned.m8n8.x4.trans.shared.b16 {%0,%1,%2,%3}, [%4];" \
        : "=r"((R)[0]), "=r"((R)[1]), "=r"((R)[2]), "=r"((R)[3]) : "r"(ADDR))

#define MMA_BF16(acc, a, b0, b1)                                              \
    asm volatile(                                                             \
        "mma.sync.aligned.m16n8k16.row.col.f32.bf16.bf16.f32 "                \
        "{%0,%1,%2,%3}, {%4,%5,%6,%7}, {%8,%9}, {%0,%1,%2,%3};"               \
        : "+f"((acc)[0]), "+f"((acc)[1]), "+f"((acc)[2]), "+f"((acc)[3])      \
        : "r"((a)[0]), "r"((a)[1]), "r"((a)[2]), "r"((a)[3]),                 \
          "r"(b0), "r"(b1))

// ---------------------------------------------------------------------------
// Split fp32 -> (hi, lo) bf16 (A-side operands)
// ---------------------------------------------------------------------------
__global__ void split_rows(const float* __restrict__ src,
                           __nv_bfloat16* __restrict__ hi,
                           __nv_bfloat16* __restrict__ lo, int n)
{
    int i = (blockIdx.x * 256 + threadIdx.x) * 4;
    if (i >= n) return;
    float4 v = *(const float4*)(src + i);
    *(uint32_t*)(hi + i)     = pack2(bfround(v.x), bfround(v.y));
    *(uint32_t*)(hi + i + 2) = pack2(bfround(v.z), bfround(v.w));
    *(uint32_t*)(lo + i)     = pack2(v.x - bfround(v.x), v.y - bfround(v.y));
    *(uint32_t*)(lo + i + 2) = pack2(v.z - bfround(v.z), v.w - bfround(v.w));
}

// ---------------------------------------------------------------------------
// Split + transpose-pack:  W[K][N] -> hi/lo u32 [N][K/2] (k-pairs packed)
// ---------------------------------------------------------------------------
__global__ void split_pack_t(const float* __restrict__ W,
                             uint32_t* __restrict__ hp,
                             uint32_t* __restrict__ lp, int K, int N)
{
    __shared__ float t[32][33];
    const int k0 = blockIdx.x * 32, n0 = blockIdx.y * 32;
    const int tx = threadIdx.x, ty = threadIdx.y;
    for (int i = ty; i < 32; i += 8)
        t[i][tx] = W[(size_t)(k0 + i) * N + n0 + tx];
    __syncthreads();
    if (tx < 16) {
        for (int i = ty; i < 32; i += 8) {
            float v0 = t[2*tx][i], v1 = t[2*tx+1][i];
            size_t o = (size_t)(n0 + i) * (K >> 1) + (k0 >> 1) + tx;
            hp[o] = pack2(bfround(v0), bfround(v1));
            lp[o] = pack2(v0 - bfround(v0), v1 - bfround(v1));
        }
    }
}

// ---------------------------------------------------------------------------
// bf16x3 GEMM with ldmatrix:  C[M,N] = A[M,K] @ B + bias   (unchanged from R6)
// ---------------------------------------------------------------------------
#define SROWB 80
#define REGB  (128*SROWB)
#define OFF_AH 0
#define OFF_AL REGB
#define OFF_BH (2*REGB)
#define OFF_BL (3*REGB)
#define STAGE  (4*REGB)
#define GEMM_SMEM (2*STAGE)

template<int OUT_SPLIT>
__global__ void __launch_bounds__(256, 2)
gemm_bf16x3(const __nv_bfloat16* __restrict__ Ah,
            const __nv_bfloat16* __restrict__ Al,
            const uint32_t* __restrict__ Bh,
            const uint32_t* __restrict__ Bl,
            const float* __restrict__ bias,
            float* __restrict__ C,
            __nv_bfloat16* __restrict__ Ch,
            __nv_bfloat16* __restrict__ Cl,
            int Ndim, int Kdim)
{
    extern __shared__ char sm[];
    const uint32_t smb = smem_u32(sm);
    const int tid = threadIdx.x;
    const int lane = tid & 31, wid = tid >> 5;
    const int warp_row = wid & 3, warp_col = wid >> 2;
    const int m0 = blockIdx.y << 7, n0 = blockIdx.x << 7;
    const int lr = lane >> 2, lc = lane & 3;
    const int KH = Kdim >> 1;

    float acc[2][8][4];
    #pragma unroll
    for (int mt = 0; mt < 2; mt++)
        #pragma unroll
        for (int nt = 0; nt < 8; nt++)
            #pragma unroll
            for (int i = 0; i < 4; i++) acc[mt][nt][i] = 0.f;

    const int crow = tid >> 2, cch = tid & 3;
    const int nk = Kdim >> 5;

    auto issue = [&](int kc) {
        const uint32_t base = smb + (kc & 1) * STAGE;
        const int k0 = kc << 5, kp0 = kc << 4;
        #pragma unroll
        for (int p = 0; p < 2; p++) {
            int row = p * 64 + crow;
            uint32_t d = base + row * SROWB + cch * 16;
            CP16(d + OFF_AH, Ah + (size_t)(m0 + row) * Kdim + k0 + cch * 8);
            CP16(d + OFF_AL, Al + (size_t)(m0 + row) * Kdim + k0 + cch * 8);
            CP16(d + OFF_BH, Bh + (size_t)(n0 + row) * KH + kp0 + cch * 4);
            CP16(d + OFF_BL, Bl + (size_t)(n0 + row) * KH + kp0 + cch * 4);
        }
        CP_COMMIT();
    };

    issue(0);
    if (nk > 1) issue(1);

    const int a_row = lane & 15, a_koff = lane & 16;
    const int b_row = (lane & 7) + ((lane & 16) ? 8 : 0);
    const int b_koff = (lane & 8) ? 16 : 0;

    for (int kc = 0; kc < nk; kc++) {
        if (kc + 1 < nk) CP_WAIT(1); else CP_WAIT(0);
        __syncthreads();
        const uint32_t base = smb + (kc & 1) * STAGE;

        #pragma unroll
        for (int ks = 0; ks < 2; ks++) {
            uint32_t ah[2][4], al[2][4];
            #pragma unroll
            for (int mt = 0; mt < 2; mt++) {
                uint32_t aa = base + OFF_AH
                            + (warp_row*32 + mt*16 + a_row) * SROWB
                            + ks*32 + a_koff;
                LDSM4(ah[mt], aa);
                LDSM4(al[mt], aa + (OFF_AL - OFF_AH));
            }
            #pragma unroll
            for (int np = 0; np < 4; np++) {
                uint32_t ba = base + OFF_BH
                            + (warp_col*64 + np*16 + b_row) * SROWB
                            + ks*32 + b_koff;
                uint32_t bh4[4], bl4[4];
                LDSM4(bh4, ba);
                LDSM4(bl4, ba + (OFF_BL - OFF_BH));
                #pragma unroll
                for (int sub = 0; sub < 2; sub++) {
                    #pragma unroll
                    for (int mt = 0; mt < 2; mt++) {
                        MMA_BF16(acc[mt][2*np+sub], ah[mt], bh4[2*sub], bh4[2*sub+1]);
                        MMA_BF16(acc[mt][2*np+sub], al[mt], bh4[2*sub], bh4[2*sub+1]);
                        MMA_BF16(acc[mt][2*np+sub], ah[mt], bl4[2*sub], bl4[2*sub+1]);
                    }
                }
            }
        }
        __syncthreads();
        if (kc + 2 < nk) issue(kc + 2);
    }

    #pragma unroll
    for (int mt = 0; mt < 2; mt++) {
        const int r0 = m0 + warp_row*32 + mt*16 + lr;
        #pragma unroll
        for (int nt = 0; nt < 8; nt++) {
            const int col = n0 + warp_col*64 + nt*8 + lc*2;
            const float2 bv = *(const float2*)(bias + col);
            float v0 = acc[mt][nt][0] + bv.x, v1 = acc[mt][nt][1] + bv.y;
            float v2 = acc[mt][nt][2] + bv.x, v3 = acc[mt][nt][3] + bv.y;
            if (OUT_SPLIT) {
                *(uint32_t*)(Ch + (size_t)r0 * Ndim + col) = pack2(v0, v1);
                *(uint32_t*)(Cl + (size_t)r0 * Ndim + col) =
                    pack2(v0 - bfround(v0), v1 - bfround(v1));
                *(uint32_t*)(Ch + (size_t)(r0+8) * Ndim + col) = pack2(v2, v3);
                *(uint32_t*)(Cl + (size_t)(r0+8) * Ndim + col) =
                    pack2(v2 - bfround(v2), v3 - bfround(v3));
            } else {
                *(float2*)(C + (size_t)r0 * Ndim + col)     = make_float2(v0, v1);
                *(float2*)(C + (size_t)(r0+8) * Ndim + col) = make_float2(v2, v3);
            }
        }
    }
}

// ---------------------------------------------------------------------------
// Tensor-core flash attention, shared latent (K == V), bf16x3 accuracy.
// s-tile 128 (halved softmax/sync overhead), diagonal masked-work skip,
// heavy-first (qt descending) CTA order.
// CTA: 256 thr (8 warps), q-tile 128 rows (warp w: rows w*16..+15).
// ---------------------------------------------------------------------------
#define KROWB 272                          // 128 bf16 = 256B data + 16B pad
#define STG_L (128*KROWB)                  // lo half offset within a stage
#define STAGE_A (2*128*KROWB)              // 69632 per stage (hi+lo)
#define Q_OFF (2*STAGE_A)                  // 139264
#define ATTN_SMEM (2*STAGE_A + 128*KROWB)  // 174080

__global__ void __launch_bounds__(256, 1)
attn_kernel(const __nv_bfloat16* __restrict__ qh,
            const __nv_bfloat16* __restrict__ ql,
            const __nv_bfloat16* __restrict__ kh,
            const __nv_bfloat16* __restrict__ kl,
            __nv_bfloat16* __restrict__ yh,
            __nv_bfloat16* __restrict__ yl)
{
    extern __shared__ char sm[];
    const uint32_t smb = smem_u32(sm);
    const int tid = threadIdx.x;
    const int lane = tid & 31, w = tid >> 5;
    const int lr = lane >> 2, lc = lane & 3;
    const int qt = (int)gridDim.x - 1 - (int)blockIdx.x;   // heavy first
    const int bhid = blockIdx.y;
    const int b = bhid >> 4, h = bhid & 15;

    const char* qbh = (const char*)(qh + ((size_t)b*TSEQ + qt*128)*QSTR + h*LDIM);
    const char* qbl = (const char*)(ql + ((size_t)b*TSEQ + qt*128)*QSTR + h*LDIM);
    const char* kbh = (const char*)(kh + (size_t)b*TSEQ*LDIM);
    const char* kbl = (const char*)(kl + (size_t)b*TSEQ*LDIM);

    // ---- Prologue: Q fragments (hi then lo through the Q staging region)
    uint32_t qfh[8][4], qfl[8][4];
    {
        const int qrow = tid >> 4, qch = tid & 15;
        #pragma unroll
        for (int p = 0; p < 8; p++) {
            int row = p*16 + qrow;
            CP16(smb + Q_OFF + row*KROWB + qch*16, qbh + (size_t)row*QSTR*2 + qch*16);
        }
        CP_COMMIT(); CP_WAIT(0); __syncthreads();
        #pragma unroll
        for (int ks = 0; ks < 8; ks++) {
            uint32_t a = smb + Q_OFF + (w*16 + (lane & 15))*KROWB + ks*32 + (lane & 16);
            LDSM4(qfh[ks], a);
        }
        __syncthreads();
        #pragma unroll
        for (int p = 0; p < 8; p++) {
            int row = p*16 + qrow;
            CP16(smb + Q_OFF + row*KROWB + qch*16, qbl + (size_t)row*QSTR*2 + qch*16);
        }
        CP_COMMIT(); CP_WAIT(0); __syncthreads();
        #pragma unroll
        for (int ks = 0; ks < 8; ks++) {
            uint32_t a = smb + Q_OFF + (w*16 + (lane & 15))*KROWB + ks*32 + (lane & 16);
            LDSM4(qfl[ks], a);
        }
        __syncthreads();
    }

    float yacc[16][4];
    #pragma unroll
    for (int nt = 0; nt < 16; nt++)
        #pragma unroll
        for (int i = 0; i < 4; i++) yacc[nt][i] = 0.f;
    float m0 = -1e30f, m1 = -1e30f, l0 = 0.f, l1 = 0.f;

    const int nkt = qt + 1;                      // 128-wide k/v tiles
    const int krow = tid >> 4, kch = tid & 15;

    auto issueK = [&](int kt) {
        const uint32_t base = smb + (kt & 1) * STAGE_A;
        #pragma unroll
        for (int p = 0; p < 8; p++) {
            int row = p*16 + krow;
            uint32_t d = base + row*KROWB + kch*16;
            CP16(d,         kbh + (size_t)(kt*128 + row)*256 + kch*16);
            CP16(d + STG_L, kbl + (size_t)(kt*128 + row)*256 + kch*16);
        }
        CP_COMMIT();
    };

    issueK(0);
    if (nkt > 1) issueK(1);

    const float scale = 0.08838834764831845f;   // 1/sqrt(128)
    const int t0g = qt*128 + w*16 + lr, t1g = t0g + 8;

    for (int kt = 0; kt < nkt; kt++) {
        if (kt + 1 < nkt) CP_WAIT(1); else CP_WAIT(0);
        __syncthreads();
        const uint32_t base = smb + (kt & 1) * STAGE_A;
        const bool diag = (kt == qt);

        // ---- S = Q K^T  (m16 x s128 x l128 per warp), bf16x3
        float sacc[16][4];
        #pragma unroll
        for (int nt = 0; nt < 16; nt++)
            #pragma unroll
            for (int i = 0; i < 4; i++) sacc[nt][i] = 0.f;

        const int sb_row = (lane & 7) + ((lane & 16) ? 8 : 0);
        const int sb_koff = (lane & 8) ? 16 : 0;
        #pragma unroll
        for (int np = 0; np < 8; np++) {
            if (diag && np > w) break;           // fully-masked s-block
            #pragma unroll
            for (int ks = 0; ks < 8; ks++) {
                uint32_t ba = base + (np*16 + sb_row)*KROWB + ks*32 + sb_koff;
                uint32_t bh4[4], bl4[4];
                LDSM4(bh4, ba);
                LDSM4(bl4, ba + STG_L);
                #pragma unroll
                for (int sub = 0; sub < 2; sub++) {
                    MMA_BF16(sacc[2*np+sub], qfh[ks], bh4[2*sub], bh4[2*sub+1]);
                    MMA_BF16(sacc[2*np+sub], qfl[ks], bh4[2*sub], bh4[2*sub+1]);
                    MMA_BF16(sacc[2*np+sub], qfh[ks], bl4[2*sub], bl4[2*sub+1]);
                }
            }
        }

        // ---- scale + causal mask (diagonal tile only)
        #pragma unroll
        for (int nt = 0; nt < 16; nt++)
            #pragma unroll
            for (int i = 0; i < 4; i++) sacc[nt][i] *= scale;
        if (diag) {
            #pragma unroll
            for (int nt = 0; nt < 16; nt++) {
                int s0 = kt*128 + nt*8 + 2*lc;
                if (s0     > t0g) sacc[nt][0] = -1e30f;
                if (s0 + 1 > t0g) sacc[nt][1] = -1e30f;
                if (s0     > t1g) sacc[nt][2] = -1e30f;
                if (s0 + 1 > t1g) sacc[nt][3] = -1e30f;
            }
        }

        // ---- online softmax (rows t0g, t1g; quad-wide shuffles)
        float mx0 = -1e30f, mx1 = -1e30f;
        #pragma unroll
        for (int nt = 0; nt < 16; nt++) {
            mx0 = fmaxf(mx0, fmaxf(sacc[nt][0], sacc[nt][1]));
            mx1 = fmaxf(mx1, fmaxf(sacc[nt][2], sacc[nt][3]));
        }
        mx0 = fmaxf(mx0, __shfl_xor_sync(0xffffffffu, mx0, 1));
        mx0 = fmaxf(mx0, __shfl_xor_sync(0xffffffffu, mx0, 2));
        mx1 = fmaxf(mx1, __shfl_xor_sync(0xffffffffu, mx1, 1));
        mx1 = fmaxf(mx1, __shfl_xor_sync(0xffffffffu, mx1, 2));
        float m0n = fmaxf(m0, mx0), m1n = fmaxf(m1, mx1);
        float c0 = __expf(m0 - m0n), c1 = __expf(m1 - m1n);
        float s0sum = 0.f, s1sum = 0.f;
        #pragma unroll
        for (int nt = 0; nt < 16; nt++) {
            float p0 = __expf(sacc[nt][0] - m0n);
            float p1 = __expf(sacc[nt][1] - m0n);
            float p2 = __expf(sacc[nt][2] - m1n);
            float p3 = __expf(sacc[nt][3] - m1n);
            s0sum += p0 + p1; s1sum += p2 + p3;
            sacc[nt][0] = p0; sacc[nt][1] = p1; sacc[nt][2] = p2; sacc[nt][3] = p3;
        }
        s0sum += __shfl_xor_sync(0xffffffffu, s0sum, 1);
        s0sum += __shfl_xor_sync(0xffffffffu, s0sum, 2);
        s1sum += __shfl_xor_sync(0xffffffffu, s1sum, 1);
        s1sum += __shfl_xor_sync(0xffffffffu, s1sum, 2);
        l0 = l0*c0 + s0sum; l1 = l1*c1 + s1sum;
        m0 = m0n; m1 = m1n;
        #pragma unroll
        for (int nt = 0; nt < 16; nt++) {
            yacc[nt][0] *= c0; yacc[nt][1] *= c0;
            yacc[nt][2] *= c1; yacc[nt][3] *= c1;
        }

        // ---- Y += P K  (m16 x l128 x s128 per warp), bf16x3, trans ldmatrix
        #pragma unroll
        for (int ks2 = 0; ks2 < 8; ks2++) {
            if (diag && ks2 > w) break;          // P == 0 beyond causal edge
            uint32_t pah[4], pal[4];
            {
                float p0 = sacc[2*ks2][0], p1 = sacc[2*ks2][1];
                float p2 = sacc[2*ks2][2], p3 = sacc[2*ks2][3];
                float q0 = sacc[2*ks2+1][0], q1 = sacc[2*ks2+1][1];
                float q2 = sacc[2*ks2+1][2], q3 = sacc[2*ks2+1][3];
                pah[0] = pack2(p0, p1); pah[1] = pack2(p2, p3);
                pah[2] = pack2(q0, q1); pah[3] = pack2(q2, q3);
                pal[0] = pack2(p0 - bfround(p0), p1 - bfround(p1));
                pal[1] = pack2(p2 - bfround(p2), p3 - bfround(p3));
                pal[2] = pack2(q0 - bfround(q0), q1 - bfround(q1));
                pal[3] = pack2(q2 - bfround(q2), q3 - bfround(q3));
            }
            #pragma unroll
            for (int np = 0; np < 8; np++) {
                uint32_t va = base + (ks2*16 + (lane & 15))*KROWB
                            + np*32 + (lane & 16);
                uint32_t vh4[4], vl4[4];
                LDSM4T(vh4, va);
                LDSM4T(vl4, va + STG_L);
                #pragma unroll
                for (int sub = 0; sub < 2; sub++) {
                    MMA_BF16(yacc[2*np+sub], pah, vh4[2*sub], vh4[2*sub+1]);
                    MMA_BF16(yacc[2*np+sub], pal, vh4[2*sub], vh4[2*sub+1]);
                    MMA_BF16(yacc[2*np+sub], pah, vl4[2*sub], vl4[2*sub+1]);
                }
            }
        }
        __syncthreads();
        if (kt + 2 < nkt) issueK(kt + 2);
    }

    // ---- Epilogue: normalize, split to bf16 hi/lo, write y
    const float li0 = 1.0f / l0, li1 = 1.0f / l1;
    #pragma unroll
    for (int nt = 0; nt < 16; nt++) {
        float v0 = yacc[nt][0]*li0, v1 = yacc[nt][1]*li0;
        float v2 = yacc[nt][2]*li1, v3 = yacc[nt][3]*li1;
        size_t o0 = ((size_t)b*TSEQ + t0g)*QSTR + h*LDIM + nt*8 + 2*lc;
        size_t o1 = o0 + (size_t)8*QSTR;
        *(uint32_t*)(yh + o0) = pack2(v0, v1);
        *(uint32_t*)(yl + o0) = pack2(v0 - bfround(v0), v1 - bfround(v1));
        *(uint32_t*)(yh + o1) = pack2(v2, v3);
        *(uint32_t*)(yl + o1) = pack2(v2 - bfround(v2), v3 - bfround(v3));
    }
}

// ---------------------------------------------------------------------------
extern "C" void kernel_launch(void* const* d_in, const int* in_sizes, int n_in,
                              void* d_out, int out_size)
{
    const float* x      = (const float*)d_in[0];
    const float* W_lat  = (const float*)d_in[1];
    const float* b_lat  = (const float*)d_in[2];
    const float* W_d    = (const float*)d_in[3];
    const float* b_d    = (const float*)d_in[4];
    const float* W_proj = (const float*)d_in[5];
    const float* b_proj = (const float*)d_in[6];
    float* out = (float*)d_out;

    __nv_bfloat16 *xh, *xl, *qhp, *qlp, *khp, *klp, *yhp, *ylp;
    uint32_t *wdh, *wdl, *wph, *wpl, *wlh, *wll;
    cudaGetSymbolAddress((void**)&xh,  g_xh);
    cudaGetSymbolAddress((void**)&xl,  g_xl);
    cudaGetSymbolAddress((void**)&qhp, g_qh);
    cudaGetSymbolAddress((void**)&qlp, g_ql);
    cudaGetSymbolAddress((void**)&khp, g_kh);
    cudaGetSymbolAddress((void**)&klp, g_kl);
    cudaGetSymbolAddress((void**)&yhp, g_yh);
    cudaGetSymbolAddress((void**)&ylp, g_yl);
    cudaGetSymbolAddress((void**)&wdh, g_wdh);
    cudaGetSymbolAddress((void**)&wdl, g_wdl);
    cudaGetSymbolAddress((void**)&wph, g_wph);
    cudaGetSymbolAddress((void**)&wpl, g_wpl);
    cudaGetSymbolAddress((void**)&wlh, g_wlh);
    cudaGetSymbolAddress((void**)&wll, g_wll);

    cudaFuncSetAttribute(gemm_bf16x3<0>,
                         cudaFuncAttributeMaxDynamicSharedMemorySize, GEMM_SMEM);
    cudaFuncSetAttribute(gemm_bf16x3<1>,
                         cudaFuncAttributeMaxDynamicSharedMemorySize, GEMM_SMEM);
    cudaFuncSetAttribute(attn_kernel,
                         cudaFuncAttributeMaxDynamicSharedMemorySize, ATTN_SMEM);

    // Preprocess
    split_rows<<<(MROWS*CEMB/4 + 255)/256, 256>>>(x, xh, xl, MROWS*CEMB);
    dim3 tb(32, 8);
    split_pack_t<<<dim3(CEMB/32, QSTR/32), tb>>>(W_d,    wdh, wdl, CEMB, QSTR);
    split_pack_t<<<dim3(QSTR/32, CEMB/32), tb>>>(W_proj, wph, wpl, QSTR, CEMB);
    split_pack_t<<<dim3(CEMB/32, LDIM/32), tb>>>(W_lat,  wlh, wll, CEMB, LDIM);

    // 1) k latent (split output)
    gemm_bf16x3<1><<<dim3(1, MROWS/128), 256, GEMM_SMEM>>>(
        xh, xl, wlh, wll, b_lat, nullptr, khp, klp, LDIM, CEMB);
    // 2) q (split output)
    gemm_bf16x3<1><<<dim3(QSTR/128, MROWS/128), 256, GEMM_SMEM>>>(
        xh, xl, wdh, wdl, b_d, nullptr, qhp, qlp, QSTR, CEMB);
    // 3) tensor-core flash attention (K == V), writes split y
    attn_kernel<<<dim3(TSEQ/128, BATCH*NHEAD), 256, ATTN_SMEM>>>(
        qhp, qlp, khp, klp, yhp, ylp);
    // 4) out = y @ W_proj + b_proj (fp32 output)
    gemm_bf16x3<0><<<dim3(CEMB/128, MROWS/128), 256, GEMM_SMEM>>>(
        yhp, ylp, wph, wpl, b_proj, out, nullptr, nullptr, CEMB, CEMB);
}

// round 8
// speedup vs baseline: 1.0881x; 1.0881x over previous
#include <cuda_runtime.h>
#include <cuda_bf16.h>
#include <cstdint>

#define BATCH 2
#define TSEQ 2048
#define CEMB 2048
#define NHEAD 16
#define LDIM 128
#define MROWS (BATCH*TSEQ)
#define QSTR (NHEAD*LDIM)   // 2048

// ---------------------------------------------------------------------------
// Scratch (__device__ globals: allocation-free rule)
// ---------------------------------------------------------------------------
__device__ __nv_bfloat16 g_xh[MROWS*CEMB], g_xl[MROWS*CEMB];   // x split
__device__ __nv_bfloat16 g_qh[MROWS*QSTR], g_ql[MROWS*QSTR];   // q split
__device__ __nv_bfloat16 g_kh[MROWS*LDIM], g_kl[MROWS*LDIM];   // k latent split
__device__ __nv_bfloat16 g_yh[MROWS*QSTR], g_yl[MROWS*QSTR];   // y split
__device__ uint32_t g_wdh[QSTR*(CEMB/2)], g_wdl[QSTR*(CEMB/2)];  // W_d  [N][K/2]
__device__ uint32_t g_wph[CEMB*(QSTR/2)], g_wpl[CEMB*(QSTR/2)];  // W_proj
__device__ uint32_t g_wlh[LDIM*(CEMB/2)], g_wll[LDIM*(CEMB/2)];  // W_lat

// ---------------------------------------------------------------------------
// Helpers
// ---------------------------------------------------------------------------
__device__ __forceinline__ uint32_t smem_u32(const void* p){
    uint32_t a;
    asm("{ .reg .u64 t; cvta.to.shared.u64 t, %1; cvt.u32.u64 %0, t; }"
        : "=r"(a) : "l"(p));
    return a;
}
__device__ __forceinline__ float bfround(float x){
    return __bfloat162float(__float2bfloat16(x));
}
__device__ __forceinline__ uint32_t pack2(float lo, float hi){
    uint32_t r;
    asm("cvt.rn.bf16x2.f32 %0, %1, %2;" : "=r"(r) : "f"(hi), "f"(lo));
    return r;
}

#define CP16(dst_u32, src_ptr) \
    asm volatile("cp.async.cg.shared.global [%0], [%1], 16;" \
                 :: "r"(dst_u32), "l"(src_ptr) : "memory")
#define CP_COMMIT() asm volatile("cp.async.commit_group;" ::: "memory")
#define CP_WAIT(n)  asm volatile("cp.async.wait_group %0;" :: "n"(n) : "memory")

#define LDSM4(R, ADDR)                                                        \
    asm volatile("ldmatrix.sync.aligned.m8n8.x4.shared.b16 {%0,%1,%2,%3}, [%4];" \
        : "=r"((R)[0]), "=r"((R)[1]), "=r"((R)[2]), "=r"((R)[3]) : "r"(ADDR))
#define LDSM4T(R, ADDR)                                                       \
    asm volatile("ldmatrix.sync.aligned.m8n8.x4.trans.shared.b16 {%0,%1,%2,%3}, [%4];" \
        : "=r"((R)[0]), "=r"((R)[1]), "=r"((R)[2]), "=r"((R)[3]) : "r"(ADDR))

#define MMA_BF16(acc, a, b0, b1)                                              \
    asm volatile(                                                             \
        "mma.sync.aligned.m16n8k16.row.col.f32.bf16.bf16.f32 "                \
        "{%0,%1,%2,%3}, {%4,%5,%6,%7}, {%8,%9}, {%0,%1,%2,%3};"               \
        : "+f"((acc)[0]), "+f"((acc)[1]), "+f"((acc)[2]), "+f"((acc)[3])      \
        : "r"((a)[0]), "r"((a)[1]), "r"((a)[2]), "r"((a)[3]),                 \
          "r"(b0), "r"(b1))

// ---------------------------------------------------------------------------
// Split fp32 -> (hi, lo) bf16 (A-side operands)
// ---------------------------------------------------------------------------
__global__ void split_rows(const float* __restrict__ src,
                           __nv_bfloat16* __restrict__ hi,
                           __nv_bfloat16* __restrict__ lo, int n)
{
    int i = (blockIdx.x * 256 + threadIdx.x) * 4;
    if (i >= n) return;
    float4 v = *(const float4*)(src + i);
    *(uint32_t*)(hi + i)     = pack2(bfround(v.x), bfround(v.y));
    *(uint32_t*)(hi + i + 2) = pack2(bfround(v.z), bfround(v.w));
    *(uint32_t*)(lo + i)     = pack2(v.x - bfround(v.x), v.y - bfround(v.y));
    *(uint32_t*)(lo + i + 2) = pack2(v.z - bfround(v.z), v.w - bfround(v.w));
}

// ---------------------------------------------------------------------------
// Split + transpose-pack:  W[K][N] -> hi/lo u32 [N][K/2] (k-pairs packed)
// ---------------------------------------------------------------------------
__global__ void split_pack_t(const float* __restrict__ W,
                             uint32_t* __restrict__ hp,
                             uint32_t* __restrict__ lp, int K, int N)
{
    __shared__ float t[32][33];
    const int k0 = blockIdx.x * 32, n0 = blockIdx.y * 32;
    const int tx = threadIdx.x, ty = threadIdx.y;
    for (int i = ty; i < 32; i += 8)
        t[i][tx] = W[(size_t)(k0 + i) * N + n0 + tx];
    __syncthreads();
    if (tx < 16) {
        for (int i = ty; i < 32; i += 8) {
            float v0 = t[2*tx][i], v1 = t[2*tx+1][i];
            size_t o = (size_t)(n0 + i) * (K >> 1) + (k0 >> 1) + tx;
            hp[o] = pack2(bfround(v0), bfround(v1));
            lp[o] = pack2(v0 - bfround(v0), v1 - bfround(v1));
        }
    }
}

// ---------------------------------------------------------------------------
// bf16x3 GEMM with ldmatrix:  C[M,N] = A[M,K] @ B + bias
// FUSE=1: last grid column (n0 >= Ndim) computes a second small GEMM
//         (same A) against B2/bias2 -> C2 with width N2 (the k latent).
// ---------------------------------------------------------------------------
#define SROWB 80
#define REGB  (128*SROWB)
#define OFF_AH 0
#define OFF_AL REGB
#define OFF_BH (2*REGB)
#define OFF_BL (3*REGB)
#define STAGE  (4*REGB)
#define GEMM_SMEM (2*STAGE)

template<int OUT_SPLIT, int FUSE>
__global__ void __launch_bounds__(256, 2)
gemm_bf16x3(const __nv_bfloat16* __restrict__ Ah,
            const __nv_bfloat16* __restrict__ Al,
            const uint32_t* __restrict__ Bh,
            const uint32_t* __restrict__ Bl,
            const float* __restrict__ bias,
            float* __restrict__ C,
            __nv_bfloat16* __restrict__ Ch,
            __nv_bfloat16* __restrict__ Cl,
            int Ndim, int Kdim,
            const uint32_t* __restrict__ B2h,
            const uint32_t* __restrict__ B2l,
            const float* __restrict__ bias2,
            __nv_bfloat16* __restrict__ C2h,
            __nv_bfloat16* __restrict__ C2l,
            int N2)
{
    extern __shared__ char sm[];
    const uint32_t smb = smem_u32(sm);
    const int tid = threadIdx.x;
    const int lane = tid & 31, wid = tid >> 5;
    const int warp_row = wid & 3, warp_col = wid >> 2;
    const int m0 = blockIdx.y << 7;
    const int lr = lane >> 2, lc = lane & 3;
    const int KH = Kdim >> 1;

    // Operand/output selection (FUSE: last grid column handles the k latent)
    const uint32_t* pBh = Bh;  const uint32_t* pBl = Bl;
    const float* pbias = bias;
    __nv_bfloat16* pCh = Ch;   __nv_bfloat16* pCl = Cl;
    int Nd = Ndim;
    int n0 = blockIdx.x << 7;
    if (FUSE && n0 >= Ndim) {
        pBh = B2h; pBl = B2l; pbias = bias2; pCh = C2h; pCl = C2l;
        Nd = N2; n0 = 0;
    }

    float acc[2][8][4];
    #pragma unroll
    for (int mt = 0; mt < 2; mt++)
        #pragma unroll
        for (int nt = 0; nt < 8; nt++)
            #pragma unroll
            for (int i = 0; i < 4; i++) acc[mt][nt][i] = 0.f;

    const int crow = tid >> 2, cch = tid & 3;
    const int nk = Kdim >> 5;

    auto issue = [&](int kc) {
        const uint32_t base = smb + (kc & 1) * STAGE;
        const int k0 = kc << 5, kp0 = kc << 4;
        #pragma unroll
        for (int p = 0; p < 2; p++) {
            int row = p * 64 + crow;
            uint32_t d = base + row * SROWB + cch * 16;
            CP16(d + OFF_AH, Ah + (size_t)(m0 + row) * Kdim + k0 + cch * 8);
            CP16(d + OFF_AL, Al + (size_t)(m0 + row) * Kdim + k0 + cch * 8);
            CP16(d + OFF_BH, pBh + (size_t)(n0 + row) * KH + kp0 + cch * 4);
            CP16(d + OFF_BL, pBl + (size_t)(n0 + row) * KH + kp0 + cch * 4);
        }
        CP_COMMIT();
    };

    issue(0);
    if (nk > 1) issue(1);

    const int a_row = lane & 15, a_koff = lane & 16;
    const int b_row = (lane & 7) + ((lane & 16) ? 8 : 0);
    const int b_koff = (lane & 8) ? 16 : 0;

    for (int kc = 0; kc < nk; kc++) {
        if (kc + 1 < nk) CP_WAIT(1); else CP_WAIT(0);
        __syncthreads();
        const uint32_t base = smb + (kc & 1) * STAGE;

        #pragma unroll
        for (int ks = 0; ks < 2; ks++) {
            uint32_t ah[2][4], al[2][4];
            #pragma unroll
            for (int mt = 0; mt < 2; mt++) {
                uint32_t aa = base + OFF_AH
                            + (warp_row*32 + mt*16 + a_row) * SROWB
                            + ks*32 + a_koff;
                LDSM4(ah[mt], aa);
                LDSM4(al[mt], aa + (OFF_AL - OFF_AH));
            }
            #pragma unroll
            for (int np = 0; np < 4; np++) {
                uint32_t ba = base + OFF_BH
                            + (warp_col*64 + np*16 + b_row) * SROWB
                            + ks*32 + b_koff;
                uint32_t bh4[4], bl4[4];
                LDSM4(bh4, ba);
                LDSM4(bl4, ba + (OFF_BL - OFF_BH));
                #pragma unroll
                for (int sub = 0; sub < 2; sub++) {
                    #pragma unroll
                    for (int mt = 0; mt < 2; mt++) {
                        MMA_BF16(acc[mt][2*np+sub], ah[mt], bh4[2*sub], bh4[2*sub+1]);
                        MMA_BF16(acc[mt][2*np+sub], al[mt], bh4[2*sub], bh4[2*sub+1]);
                        MMA_BF16(acc[mt][2*np+sub], ah[mt], bl4[2*sub], bl4[2*sub+1]);
                    }
                }
            }
        }
        __syncthreads();
        if (kc + 2 < nk) issue(kc + 2);
    }

    #pragma unroll
    for (int mt = 0; mt < 2; mt++) {
        const int r0 = m0 + warp_row*32 + mt*16 + lr;
        #pragma unroll
        for (int nt = 0; nt < 8; nt++) {
            const int col = n0 + warp_col*64 + nt*8 + lc*2;
            const float2 bv = *(const float2*)(pbias + col);
            float v0 = acc[mt][nt][0] + bv.x, v1 = acc[mt][nt][1] + bv.y;
            float v2 = acc[mt][nt][2] + bv.x, v3 = acc[mt][nt][3] + bv.y;
            if (OUT_SPLIT) {
                *(uint32_t*)(pCh + (size_t)r0 * Nd + col) = pack2(v0, v1);
                *(uint32_t*)(pCl + (size_t)r0 * Nd + col) =
                    pack2(v0 - bfround(v0), v1 - bfround(v1));
                *(uint32_t*)(pCh + (size_t)(r0+8) * Nd + col) = pack2(v2, v3);
                *(uint32_t*)(pCl + (size_t)(r0+8) * Nd + col) =
                    pack2(v2 - bfround(v2), v3 - bfround(v3));
            } else {
                *(float2*)(C + (size_t)r0 * Nd + col)     = make_float2(v0, v1);
                *(float2*)(C + (size_t)(r0+8) * Nd + col) = make_float2(v2, v3);
            }
        }
    }
}

// ---------------------------------------------------------------------------
// Tensor-core flash attention, shared latent (K == V), bf16x3 accuracy.
// R6 structure (s-tile 64) + heavy-first qt order + exact masked-block skips
// + P-fragment precompute before the Y mma loop.
// CTA: 256 thr (8 warps), q-tile 128 rows (warp w: rows w*16..+15).
// ---------------------------------------------------------------------------
#define KROWB 272                        // 128 bf16 = 256B data + 16B pad
#define STG_L (64*KROWB)                 // lo half offset within a stage
#define STAGE_A (2*64*KROWB)             // 34816 per stage (hi+lo)
#define Q_OFF (2*STAGE_A)                // 69632
#define ATTN_SMEM (2*STAGE_A + 128*KROWB)  // 104448

__global__ void __launch_bounds__(256, 1)
attn_kernel(const __nv_bfloat16* __restrict__ qh,
            const __nv_bfloat16* __restrict__ ql,
            const __nv_bfloat16* __restrict__ kh,
            const __nv_bfloat16* __restrict__ kl,
            __nv_bfloat16* __restrict__ yh,
            __nv_bfloat16* __restrict__ yl)
{
    extern __shared__ char sm[];
    const uint32_t smb = smem_u32(sm);
    const int tid = threadIdx.x;
    const int lane = tid & 31, w = tid >> 5;
    const int lr = lane >> 2, lc = lane & 3;
    const int qt = (int)gridDim.x - 1 - (int)blockIdx.x;   // heavy first
    const int bhid = blockIdx.y;
    const int b = bhid >> 4, h = bhid & 15;

    const char* qbh = (const char*)(qh + ((size_t)b*TSEQ + qt*128)*QSTR + h*LDIM);
    const char* qbl = (const char*)(ql + ((size_t)b*TSEQ + qt*128)*QSTR + h*LDIM);
    const char* kbh = (const char*)(kh + (size_t)b*TSEQ*LDIM);
    const char* kbl = (const char*)(kl + (size_t)b*TSEQ*LDIM);

    // ---- Prologue: Q fragments (hi then lo through the Q staging region)
    uint32_t qfh[8][4], qfl[8][4];
    {
        const int qrow = tid >> 4, qch = tid & 15;
        #pragma unroll
        for (int p = 0; p < 8; p++) {
            int row = p*16 + qrow;
            CP16(smb + Q_OFF + row*KROWB + qch*16, qbh + (size_t)row*QSTR*2 + qch*16);
        }
        CP_COMMIT(); CP_WAIT(0); __syncthreads();
        #pragma unroll
        for (int ks = 0; ks < 8; ks++) {
            uint32_t a = smb + Q_OFF + (w*16 + (lane & 15))*KROWB + ks*32 + (lane & 16);
            LDSM4(qfh[ks], a);
        }
        __syncthreads();
        #pragma unroll
        for (int p = 0; p < 8; p++) {
            int row = p*16 + qrow;
            CP16(smb + Q_OFF + row*KROWB + qch*16, qbl + (size_t)row*QSTR*2 + qch*16);
        }
        CP_COMMIT(); CP_WAIT(0); __syncthreads();
        #pragma unroll
        for (int ks = 0; ks < 8; ks++) {
            uint32_t a = smb + Q_OFF + (w*16 + (lane & 15))*KROWB + ks*32 + (lane & 16);
            LDSM4(qfl[ks], a);
        }
        __syncthreads();
    }

    float yacc[16][4];
    #pragma unroll
    for (int nt = 0; nt < 16; nt++)
        #pragma unroll
        for (int i = 0; i < 4; i++) yacc[nt][i] = 0.f;
    float m0 = -1e30f, m1 = -1e30f, l0 = 0.f, l1 = 0.f;

    const int nkt = 2*qt + 2;
    const int krow = tid >> 4, kch = tid & 15;

    auto issueK = [&](int kt) {
        const uint32_t base = smb + (kt & 1) * STAGE_A;
        #pragma unroll
        for (int p = 0; p < 4; p++) {
            int row = p*16 + krow;
            uint32_t d = base + row*KROWB + kch*16;
            CP16(d,         kbh + (size_t)(kt*64 + row)*256 + kch*16);
            CP16(d + STG_L, kbl + (size_t)(kt*64 + row)*256 + kch*16);
        }
        CP_COMMIT();
    };

    issueK(0);
    if (nkt > 1) issueK(1);

    const float scale = 0.08838834764831845f;   // 1/sqrt(128)
    const int t0g = qt*128 + w*16 + lr, t1g = t0g + 8;
    const int wmax = qt*128 + w*16 + 15;        // warp-uniform max row

    for (int kt = 0; kt < nkt; kt++) {
        if (kt + 1 < nkt) CP_WAIT(1); else CP_WAIT(0);
        __syncthreads();
        const uint32_t base = smb + (kt & 1) * STAGE_A;
        const bool diagband = (kt >= 2*qt);
        const bool wskip = diagband && (kt*64 > wmax);   // fully masked tile

        if (!wskip) {
            // ---- S = Q K^T  (m16 x s64 x l128 per warp), bf16x3
            float sacc[8][4];
            #pragma unroll
            for (int nt = 0; nt < 8; nt++)
                #pragma unroll
                for (int i = 0; i < 4; i++) sacc[nt][i] = 0.f;

            const int sb_row = (lane & 7) + ((lane & 16) ? 8 : 0);
            const int sb_koff = (lane & 8) ? 16 : 0;
            #pragma unroll
            for (int np = 0; np < 4; np++) {
                if (diagband && kt*64 + np*16 > wmax) break;  // fully masked
                #pragma unroll
                for (int ks = 0; ks < 8; ks++) {
                    uint32_t ba = base + (np*16 + sb_row)*KROWB + ks*32 + sb_koff;
                    uint32_t bh4[4], bl4[4];
                    LDSM4(bh4, ba);
                    LDSM4(bl4, ba + STG_L);
                    #pragma unroll
                    for (int sub = 0; sub < 2; sub++) {
                        MMA_BF16(sacc[2*np+sub], qfh[ks], bh4[2*sub], bh4[2*sub+1]);
                        MMA_BF16(sacc[2*np+sub], qfl[ks], bh4[2*sub], bh4[2*sub+1]);
                        MMA_BF16(sacc[2*np+sub], qfh[ks], bl4[2*sub], bl4[2*sub+1]);
                    }
                }
            }

            // ---- scale + causal mask (diagonal band only)
            #pragma unroll
            for (int nt = 0; nt < 8; nt++)
                #pragma unroll
                for (int i = 0; i < 4; i++) sacc[nt][i] *= scale;
            if (diagband) {
                #pragma unroll
                for (int nt = 0; nt < 8; nt++) {
                    int s0 = kt*64 + nt*8 + 2*lc;
                    if (s0     > t0g) sacc[nt][0] = -1e30f;
                    if (s0 + 1 > t0g) sacc[nt][1] = -1e30f;
                    if (s0     > t1g) sacc[nt][2] = -1e30f;
                    if (s0 + 1 > t1g) sacc[nt][3] = -1e30f;
                }
            }

            // ---- online softmax (rows t0g, t1g; quad-wide shuffles)
            float mx0 = -1e30f, mx1 = -1e30f;
            #pragma unroll
            for (int nt = 0; nt < 8; nt++) {
                mx0 = fmaxf(mx0, fmaxf(sacc[nt][0], sacc[nt][1]));
                mx1 = fmaxf(mx1, fmaxf(sacc[nt][2], sacc[nt][3]));
            }
            mx0 = fmaxf(mx0, __shfl_xor_sync(0xffffffffu, mx0, 1));
            mx0 = fmaxf(mx0, __shfl_xor_sync(0xffffffffu, mx0, 2));
            mx1 = fmaxf(mx1, __shfl_xor_sync(0xffffffffu, mx1, 1));
            mx1 = fmaxf(mx1, __shfl_xor_sync(0xffffffffu, mx1, 2));
            float m0n = fmaxf(m0, mx0), m1n = fmaxf(m1, mx1);
            float c0 = __expf(m0 - m0n), c1 = __expf(m1 - m1n);
            float s0sum = 0.f, s1sum = 0.f;
            #pragma unroll
            for (int nt = 0; nt < 8; nt++) {
                float p0 = __expf(sacc[nt][0] - m0n);
                float p1 = __expf(sacc[nt][1] - m0n);
                float p2 = __expf(sacc[nt][2] - m1n);
                float p3 = __expf(sacc[nt][3] - m1n);
                s0sum += p0 + p1; s1sum += p2 + p3;
                sacc[nt][0] = p0; sacc[nt][1] = p1;
                sacc[nt][2] = p2; sacc[nt][3] = p3;
            }
            s0sum += __shfl_xor_sync(0xffffffffu, s0sum, 1);
            s0sum += __shfl_xor_sync(0xffffffffu, s0sum, 2);
            s1sum += __shfl_xor_sync(0xffffffffu, s1sum, 1);
            s1sum += __shfl_xor_sync(0xffffffffu, s1sum, 2);
            l0 = l0*c0 + s0sum; l1 = l1*c1 + s1sum;
            m0 = m0n; m1 = m1n;
            #pragma unroll
            for (int nt = 0; nt < 16; nt++) {
                yacc[nt][0] *= c0; yacc[nt][1] *= c0;
                yacc[nt][2] *= c1; yacc[nt][3] *= c1;
            }

            // ---- Precompute ALL P fragments (hi + lo), then pure mma loop
            uint32_t pah[4][4], pal[4][4];
            #pragma unroll
            for (int ks2 = 0; ks2 < 4; ks2++) {
                float p0 = sacc[2*ks2][0], p1 = sacc[2*ks2][1];
                float p2 = sacc[2*ks2][2], p3 = sacc[2*ks2][3];
                float q0 = sacc[2*ks2+1][0], q1 = sacc[2*ks2+1][1];
                float q2 = sacc[2*ks2+1][2], q3 = sacc[2*ks2+1][3];
                pah[ks2][0] = pack2(p0, p1); pah[ks2][1] = pack2(p2, p3);
                pah[ks2][2] = pack2(q0, q1); pah[ks2][3] = pack2(q2, q3);
                pal[ks2][0] = pack2(p0 - bfround(p0), p1 - bfround(p1));
                pal[ks2][1] = pack2(p2 - bfround(p2), p3 - bfround(p3));
                pal[ks2][2] = pack2(q0 - bfround(q0), q1 - bfround(q1));
                pal[ks2][3] = pack2(q2 - bfround(q2), q3 - bfround(q3));
            }

            // ---- Y += P K  (m16 x l128 x s64 per warp), trans ldmatrix
            #pragma unroll
            for (int ks2 = 0; ks2 < 4; ks2++) {
                if (diagband && kt*64 + ks2*16 > wmax) break;  // P block == 0
                #pragma unroll
                for (int np = 0; np < 8; np++) {
                    uint32_t va = base + (ks2*16 + (lane & 15))*KROWB
                                + np*32 + (lane & 16);
                    uint32_t vh4[4], vl4[4];
                    LDSM4T(vh4, va);
                    LDSM4T(vl4, va + STG_L);
                    #pragma unroll
                    for (int sub = 0; sub < 2; sub++) {
                        MMA_BF16(yacc[2*np+sub], pah[ks2], vh4[2*sub], vh4[2*sub+1]);
                        MMA_BF16(yacc[2*np+sub], pal[ks2], vh4[2*sub], vh4[2*sub+1]);
                        MMA_BF16(yacc[2*np+sub], pah[ks2], vl4[2*sub], vl4[2*sub+1]);
                    }
                }
            }
        }
        __syncthreads();
        if (kt + 2 < nkt) issueK(kt + 2);
    }

    // ---- Epilogue: normalize, split to bf16 hi/lo, write y
    const float li0 = 1.0f / l0, li1 = 1.0f / l1;
    #pragma unroll
    for (int nt = 0; nt < 16; nt++) {
        float v0 = yacc[nt][0]*li0, v1 = yacc[nt][1]*li0;
        float v2 = yacc[nt][2]*li1, v3 = yacc[nt][3]*li1;
        size_t o0 = ((size_t)b*TSEQ + t0g)*QSTR + h*LDIM + nt*8 + 2*lc;
        size_t o1 = o0 + (size_t)8*QSTR;
        *(uint32_t*)(yh + o0) = pack2(v0, v1);
        *(uint32_t*)(yl + o0) = pack2(v0 - bfround(v0), v1 - bfround(v1));
        *(uint32_t*)(yh + o1) = pack2(v2, v3);
        *(uint32_t*)(yl + o1) = pack2(v2 - bfround(v2), v3 - bfround(v3));
    }
}

// ---------------------------------------------------------------------------
extern "C" void kernel_launch(void* const* d_in, const int* in_sizes, int n_in,
                              void* d_out, int out_size)
{
    const float* x      = (const float*)d_in[0];
    const float* W_lat  = (const float*)d_in[1];
    const float* b_lat  = (const float*)d_in[2];
    const float* W_d    = (const float*)d_in[3];
    const float* b_d    = (const float*)d_in[4];
    const float* W_proj = (const float*)d_in[5];
    const float* b_proj = (const float*)d_in[6];
    float* out = (float*)d_out;

    __nv_bfloat16 *xh, *xl, *qhp, *qlp, *khp, *klp, *yhp, *ylp;
    uint32_t *wdh, *wdl, *wph, *wpl, *wlh, *wll;
    cudaGetSymbolAddress((void**)&xh,  g_xh);
    cudaGetSymbolAddress((void**)&xl,  g_xl);
    cudaGetSymbolAddress((void**)&qhp, g_qh);
    cudaGetSymbolAddress((void**)&qlp, g_ql);
    cudaGetSymbolAddress((void**)&khp, g_kh);
    cudaGetSymbolAddress((void**)&klp, g_kl);
    cudaGetSymbolAddress((void**)&yhp, g_yh);
    cudaGetSymbolAddress((void**)&ylp, g_yl);
    cudaGetSymbolAddress((void**)&wdh, g_wdh);
    cudaGetSymbolAddress((void**)&wdl, g_wdl);
    cudaGetSymbolAddress((void**)&wph, g_wph);
    cudaGetSymbolAddress((void**)&wpl, g_wpl);
    cudaGetSymbolAddress((void**)&wlh, g_wlh);
    cudaGetSymbolAddress((void**)&wll, g_wll);

    cudaFuncSetAttribute((const void*)gemm_bf16x3<0,0>,
                         cudaFuncAttributeMaxDynamicSharedMemorySize, GEMM_SMEM);
    cudaFuncSetAttribute((const void*)gemm_bf16x3<1,1>,
                         cudaFuncAttributeMaxDynamicSharedMemorySize, GEMM_SMEM);
    cudaFuncSetAttribute((const void*)attn_kernel,
                         cudaFuncAttributeMaxDynamicSharedMemorySize, ATTN_SMEM);

    // Preprocess
    split_rows<<<(MROWS*CEMB/4 + 255)/256, 256>>>(x, xh, xl, MROWS*CEMB);
    dim3 tb(32, 8);
    split_pack_t<<<dim3(CEMB/32, QSTR/32), tb>>>(W_d,    wdh, wdl, CEMB, QSTR);
    split_pack_t<<<dim3(QSTR/32, CEMB/32), tb>>>(W_proj, wph, wpl, QSTR, CEMB);
    split_pack_t<<<dim3(CEMB/32, LDIM/32), tb>>>(W_lat,  wlh, wll, CEMB, LDIM);

    // 1+2) q = x@W_d + b_d  FUSED WITH  k = x@W_lat + b_lat  (17th column)
    gemm_bf16x3<1,1><<<dim3(QSTR/128 + 1, MROWS/128), 256, GEMM_SMEM>>>(
        xh, xl, wdh, wdl, b_d, nullptr, qhp, qlp, QSTR, CEMB,
        wlh, wll, b_lat, khp, klp, LDIM);
    // 3) tensor-core flash attention (K == V), writes split y
    attn_kernel<<<dim3(TSEQ/128, BATCH*NHEAD), 256, ATTN_SMEM>>>(
        qhp, qlp, khp, klp, yhp, ylp);
    // 4) out = y @ W_proj + b_proj (fp32 output)
    gemm_bf16x3<0,0><<<dim3(CEMB/128, MROWS/128), 256, GEMM_SMEM>>>(
        yhp, ylp, wph, wpl, b_proj, out, nullptr, nullptr, CEMB, CEMB,
        nullptr, nullptr, nullptr, nullptr, nullptr, 0);
}

// round 9
// speedup vs baseline: 1.1918x; 1.0953x over previous
#include <cuda_runtime.h>
#include <cuda_bf16.h>
#include <cuda_fp16.h>
#include <cstdint>

#define BATCH 2
#define TSEQ 2048
#define CEMB 2048
#define NHEAD 16
#define LDIM 128
#define MROWS (BATCH*TSEQ)
#define QSTR (NHEAD*LDIM)   // 2048

// ---------------------------------------------------------------------------
// Scratch (__device__ globals: allocation-free rule)
// ---------------------------------------------------------------------------
__device__ __nv_bfloat16 g_xh[MROWS*CEMB], g_xl[MROWS*CEMB];   // x split (bf16)
__device__ __nv_bfloat16 g_qh[MROWS*QSTR], g_ql[MROWS*QSTR];   // q split (bf16)
__device__ __nv_bfloat16 g_kh[MROWS*LDIM], g_kl[MROWS*LDIM];   // k split (bf16)
__device__ __half        g_yh[MROWS*QSTR], g_yl[MROWS*QSTR];   // y split (fp16)
__device__ uint32_t g_wdh[QSTR*(CEMB/2)], g_wdl[QSTR*(CEMB/2)];  // W_d bf16 pairs
__device__ uint32_t g_wlh[LDIM*(CEMB/2)], g_wll[LDIM*(CEMB/2)];  // W_lat bf16
__device__ uint32_t g_wph[CEMB*(QSTR/2)];                        // W_proj fp16 HI

// ---------------------------------------------------------------------------
// Helpers
// ---------------------------------------------------------------------------
__device__ __forceinline__ uint32_t smem_u32(const void* p){
    uint32_t a;
    asm("{ .reg .u64 t; cvta.to.shared.u64 t, %1; cvt.u32.u64 %0, t; }"
        : "=r"(a) : "l"(p));
    return a;
}
__device__ __forceinline__ float bfround(float x){
    return __bfloat162float(__float2bfloat16(x));
}
__device__ __forceinline__ float hfround(float x){
    return __half2float(__float2half_rn(x));
}
__device__ __forceinline__ uint32_t pack2(float lo, float hi){
    uint32_t r;
    asm("cvt.rn.bf16x2.f32 %0, %1, %2;" : "=r"(r) : "f"(hi), "f"(lo));
    return r;
}
__device__ __forceinline__ uint32_t pack2h(float lo, float hi){
    uint32_t r;
    asm("cvt.rn.f16x2.f32 %0, %1, %2;" : "=r"(r) : "f"(hi), "f"(lo));
    return r;
}

#define CP16(dst_u32, src_ptr) \
    asm volatile("cp.async.cg.shared.global [%0], [%1], 16;" \
                 :: "r"(dst_u32), "l"(src_ptr) : "memory")
#define CP_COMMIT() asm volatile("cp.async.commit_group;" ::: "memory")
#define CP_WAIT(n)  asm volatile("cp.async.wait_group %0;" :: "n"(n) : "memory")

#define LDSM4(R, ADDR)                                                        \
    asm volatile("ldmatrix.sync.aligned.m8n8.x4.shared.b16 {%0,%1,%2,%3}, [%4];" \
        : "=r"((R)[0]), "=r"((R)[1]), "=r"((R)[2]), "=r"((R)[3]) : "r"(ADDR))
#define LDSM4T(R, ADDR)                                                       \
    asm volatile("ldmatrix.sync.aligned.m8n8.x4.trans.shared.b16 {%0,%1,%2,%3}, [%4];" \
        : "=r"((R)[0]), "=r"((R)[1]), "=r"((R)[2]), "=r"((R)[3]) : "r"(ADDR))

#define MMA_BF16(acc, a, b0, b1)                                              \
    asm volatile(                                                             \
        "mma.sync.aligned.m16n8k16.row.col.f32.bf16.bf16.f32 "                \
        "{%0,%1,%2,%3}, {%4,%5,%6,%7}, {%8,%9}, {%0,%1,%2,%3};"               \
        : "+f"((acc)[0]), "+f"((acc)[1]), "+f"((acc)[2]), "+f"((acc)[3])      \
        : "r"((a)[0]), "r"((a)[1]), "r"((a)[2]), "r"((a)[3]),                 \
          "r"(b0), "r"(b1))

#define MMA_F16(acc, a, b0, b1)                                               \
    asm volatile(                                                             \
        "mma.sync.aligned.m16n8k16.row.col.f32.f16.f16.f32 "                  \
        "{%0,%1,%2,%3}, {%4,%5,%6,%7}, {%8,%9}, {%0,%1,%2,%3};"               \
        : "+f"((acc)[0]), "+f"((acc)[1]), "+f"((acc)[2]), "+f"((acc)[3])      \
        : "r"((a)[0]), "r"((a)[1]), "r"((a)[2]), "r"((a)[3]),                 \
          "r"(b0), "r"(b1))

// ---------------------------------------------------------------------------
// Split fp32 -> (hi, lo) bf16
// ---------------------------------------------------------------------------
__global__ void split_rows(const float* __restrict__ src,
                           __nv_bfloat16* __restrict__ hi,
                           __nv_bfloat16* __restrict__ lo, int n)
{
    int i = (blockIdx.x * 256 + threadIdx.x) * 4;
    if (i >= n) return;
    float4 v = *(const float4*)(src + i);
    *(uint32_t*)(hi + i)     = pack2(bfround(v.x), bfround(v.y));
    *(uint32_t*)(hi + i + 2) = pack2(bfround(v.z), bfround(v.w));
    *(uint32_t*)(lo + i)     = pack2(v.x - bfround(v.x), v.y - bfround(v.y));
    *(uint32_t*)(lo + i + 2) = pack2(v.z - bfround(v.z), v.w - bfround(v.w));
}

// ---------------------------------------------------------------------------
// Split + transpose-pack (bf16 pairs):  W[K][N] -> hi/lo u32 [N][K/2]
// ---------------------------------------------------------------------------
__global__ void split_pack_t(const float* __restrict__ W,
                             uint32_t* __restrict__ hp,
                             uint32_t* __restrict__ lp, int K, int N)
{
    __shared__ float t[32][33];
    const int k0 = blockIdx.x * 32, n0 = blockIdx.y * 32;
    const int tx = threadIdx.x, ty = threadIdx.y;
    for (int i = ty; i < 32; i += 8)
        t[i][tx] = W[(size_t)(k0 + i) * N + n0 + tx];
    __syncthreads();
    if (tx < 16) {
        for (int i = ty; i < 32; i += 8) {
            float v0 = t[2*tx][i], v1 = t[2*tx+1][i];
            size_t o = (size_t)(n0 + i) * (K >> 1) + (k0 >> 1) + tx;
            hp[o] = pack2(bfround(v0), bfround(v1));
            lp[o] = pack2(v0 - bfround(v0), v1 - bfround(v1));
        }
    }
}

// ---------------------------------------------------------------------------
// Transpose-pack fp16 HI only:  W[K][N] -> u32 [N][K/2] (f16 k-pairs)
// ---------------------------------------------------------------------------
__global__ void split_pack_h(const float* __restrict__ W,
                             uint32_t* __restrict__ hp, int K, int N)
{
    __shared__ float t[32][33];
    const int k0 = blockIdx.x * 32, n0 = blockIdx.y * 32;
    const int tx = threadIdx.x, ty = threadIdx.y;
    for (int i = ty; i < 32; i += 8)
        t[i][tx] = W[(size_t)(k0 + i) * N + n0 + tx];
    __syncthreads();
    if (tx < 16) {
        for (int i = ty; i < 32; i += 8) {
            float v0 = t[2*tx][i], v1 = t[2*tx+1][i];
            size_t o = (size_t)(n0 + i) * (K >> 1) + (k0 >> 1) + tx;
            hp[o] = pack2h(v0, v1);
        }
    }
}

// ---------------------------------------------------------------------------
// bf16x3 GEMM with ldmatrix (q/k path, FUSE handles the latent column)
// ---------------------------------------------------------------------------
#define SROWB 80
#define REGB  (128*SROWB)
#define OFF_AH 0
#define OFF_AL REGB
#define OFF_BH (2*REGB)
#define OFF_BL (3*REGB)
#define STAGE  (4*REGB)
#define GEMM_SMEM (2*STAGE)

__global__ void __launch_bounds__(256, 2)
gemm_bf16x3(const __nv_bfloat16* __restrict__ Ah,
            const __nv_bfloat16* __restrict__ Al,
            const uint32_t* __restrict__ Bh,
            const uint32_t* __restrict__ Bl,
            const float* __restrict__ bias,
            __nv_bfloat16* __restrict__ Ch,
            __nv_bfloat16* __restrict__ Cl,
            int Ndim, int Kdim,
            const uint32_t* __restrict__ B2h,
            const uint32_t* __restrict__ B2l,
            const float* __restrict__ bias2,
            __nv_bfloat16* __restrict__ C2h,
            __nv_bfloat16* __restrict__ C2l,
            int N2)
{
    extern __shared__ char sm[];
    const uint32_t smb = smem_u32(sm);
    const int tid = threadIdx.x;
    const int lane = tid & 31, wid = tid >> 5;
    const int warp_row = wid & 3, warp_col = wid >> 2;
    const int m0 = blockIdx.y << 7;
    const int lr = lane >> 2, lc = lane & 3;
    const int KH = Kdim >> 1;

    const uint32_t* pBh = Bh;  const uint32_t* pBl = Bl;
    const float* pbias = bias;
    __nv_bfloat16* pCh = Ch;   __nv_bfloat16* pCl = Cl;
    int Nd = Ndim;
    int n0 = blockIdx.x << 7;
    if (n0 >= Ndim) {               // fused latent column
        pBh = B2h; pBl = B2l; pbias = bias2; pCh = C2h; pCl = C2l;
        Nd = N2; n0 = 0;
    }

    float acc[2][8][4];
    #pragma unroll
    for (int mt = 0; mt < 2; mt++)
        #pragma unroll
        for (int nt = 0; nt < 8; nt++)
            #pragma unroll
            for (int i = 0; i < 4; i++) acc[mt][nt][i] = 0.f;

    const int crow = tid >> 2, cch = tid & 3;
    const int nk = Kdim >> 5;

    auto issue = [&](int kc) {
        const uint32_t base = smb + (kc & 1) * STAGE;
        const int k0 = kc << 5, kp0 = kc << 4;
        #pragma unroll
        for (int p = 0; p < 2; p++) {
            int row = p * 64 + crow;
            uint32_t d = base + row * SROWB + cch * 16;
            CP16(d + OFF_AH, Ah + (size_t)(m0 + row) * Kdim + k0 + cch * 8);
            CP16(d + OFF_AL, Al + (size_t)(m0 + row) * Kdim + k0 + cch * 8);
            CP16(d + OFF_BH, pBh + (size_t)(n0 + row) * KH + kp0 + cch * 4);
            CP16(d + OFF_BL, pBl + (size_t)(n0 + row) * KH + kp0 + cch * 4);
        }
        CP_COMMIT();
    };

    issue(0);
    if (nk > 1) issue(1);

    const int a_row = lane & 15, a_koff = lane & 16;
    const int b_row = (lane & 7) + ((lane & 16) ? 8 : 0);
    const int b_koff = (lane & 8) ? 16 : 0;

    for (int kc = 0; kc < nk; kc++) {
        if (kc + 1 < nk) CP_WAIT(1); else CP_WAIT(0);
        __syncthreads();
        const uint32_t base = smb + (kc & 1) * STAGE;

        #pragma unroll
        for (int ks = 0; ks < 2; ks++) {
            uint32_t ah[2][4], al[2][4];
            #pragma unroll
            for (int mt = 0; mt < 2; mt++) {
                uint32_t aa = base + OFF_AH
                            + (warp_row*32 + mt*16 + a_row) * SROWB
                            + ks*32 + a_koff;
                LDSM4(ah[mt], aa);
                LDSM4(al[mt], aa + (OFF_AL - OFF_AH));
            }
            #pragma unroll
            for (int np = 0; np < 4; np++) {
                uint32_t ba = base + OFF_BH
                            + (warp_col*64 + np*16 + b_row) * SROWB
                            + ks*32 + b_koff;
                uint32_t bh4[4], bl4[4];
                LDSM4(bh4, ba);
                LDSM4(bl4, ba + (OFF_BL - OFF_BH));
                #pragma unroll
                for (int sub = 0; sub < 2; sub++) {
                    #pragma unroll
                    for (int mt = 0; mt < 2; mt++) {
                        MMA_BF16(acc[mt][2*np+sub], ah[mt], bh4[2*sub], bh4[2*sub+1]);
                        MMA_BF16(acc[mt][2*np+sub], al[mt], bh4[2*sub], bh4[2*sub+1]);
                        MMA_BF16(acc[mt][2*np+sub], ah[mt], bl4[2*sub], bl4[2*sub+1]);
                    }
                }
            }
        }
        __syncthreads();
        if (kc + 2 < nk) issue(kc + 2);
    }

    #pragma unroll
    for (int mt = 0; mt < 2; mt++) {
        const int r0 = m0 + warp_row*32 + mt*16 + lr;
        #pragma unroll
        for (int nt = 0; nt < 8; nt++) {
            const int col = n0 + warp_col*64 + nt*8 + lc*2;
            const float2 bv = *(const float2*)(pbias + col);
            float v0 = acc[mt][nt][0] + bv.x, v1 = acc[mt][nt][1] + bv.y;
            float v2 = acc[mt][nt][2] + bv.x, v3 = acc[mt][nt][3] + bv.y;
            *(uint32_t*)(pCh + (size_t)r0 * Nd + col) = pack2(v0, v1);
            *(uint32_t*)(pCl + (size_t)r0 * Nd + col) =
                pack2(v0 - bfround(v0), v1 - bfround(v1));
            *(uint32_t*)(pCh + (size_t)(r0+8) * Nd + col) = pack2(v2, v3);
            *(uint32_t*)(pCl + (size_t)(r0+8) * Nd + col) =
                pack2(v2 - bfround(v2), v3 - bfround(v3));
        }
    }
}

// ---------------------------------------------------------------------------
// fp16 2-mma GEMM (proj path):  C = (Ah+Al) @ Bh + bias, fp32 out.
// A: fp16 hi/lo [M][K]; B: fp16 u32 [N][K/2] HI ONLY.
// Error = A @ Blo ~ 2^-12 rel, enters output linearly (no softmax chain).
// ---------------------------------------------------------------------------
#define F_OFF_AH 0
#define F_OFF_AL REGB
#define F_OFF_BH (2*REGB)
#define F_STAGE  (3*REGB)                 // 30720
#define GEMM_SMEM_F16 (2*F_STAGE)         // 61440

__global__ void __launch_bounds__(256, 2)
gemm_f16x2(const __half* __restrict__ Ah,
           const __half* __restrict__ Al,
           const uint32_t* __restrict__ Bh,
           const float* __restrict__ bias,
           float* __restrict__ C,
           int Ndim, int Kdim)
{
    extern __shared__ char sm[];
    const uint32_t smb = smem_u32(sm);
    const int tid = threadIdx.x;
    const int lane = tid & 31, wid = tid >> 5;
    const int warp_row = wid & 3, warp_col = wid >> 2;
    const int m0 = blockIdx.y << 7, n0 = blockIdx.x << 7;
    const int lr = lane >> 2, lc = lane & 3;
    const int KH = Kdim >> 1;

    float acc[2][8][4];
    #pragma unroll
    for (int mt = 0; mt < 2; mt++)
        #pragma unroll
        for (int nt = 0; nt < 8; nt++)
            #pragma unroll
            for (int i = 0; i < 4; i++) acc[mt][nt][i] = 0.f;

    const int crow = tid >> 2, cch = tid & 3;
    const int nk = Kdim >> 5;

    auto issue = [&](int kc) {
        const uint32_t base = smb + (kc & 1) * F_STAGE;
        const int k0 = kc << 5, kp0 = kc << 4;
        #pragma unroll
        for (int p = 0; p < 2; p++) {
            int row = p * 64 + crow;
            uint32_t d = base + row * SROWB + cch * 16;
            CP16(d + F_OFF_AH, Ah + (size_t)(m0 + row) * Kdim + k0 + cch * 8);
            CP16(d + F_OFF_AL, Al + (size_t)(m0 + row) * Kdim + k0 + cch * 8);
            CP16(d + F_OFF_BH, Bh + (size_t)(n0 + row) * KH + kp0 + cch * 4);
        }
        CP_COMMIT();
    };

    issue(0);
    if (nk > 1) issue(1);

    const int a_row = lane & 15, a_koff = lane & 16;
    const int b_row = (lane & 7) + ((lane & 16) ? 8 : 0);
    const int b_koff = (lane & 8) ? 16 : 0;

    for (int kc = 0; kc < nk; kc++) {
        if (kc + 1 < nk) CP_WAIT(1); else CP_WAIT(0);
        __syncthreads();
        const uint32_t base = smb + (kc & 1) * F_STAGE;

        #pragma unroll
        for (int ks = 0; ks < 2; ks++) {
            uint32_t ah[2][4], al[2][4];
            #pragma unroll
            for (int mt = 0; mt < 2; mt++) {
                uint32_t aa = base + F_OFF_AH
                            + (warp_row*32 + mt*16 + a_row) * SROWB
                            + ks*32 + a_koff;
                LDSM4(ah[mt], aa);
                LDSM4(al[mt], aa + (F_OFF_AL - F_OFF_AH));
            }
            #pragma unroll
            for (int np = 0; np < 4; np++) {
                uint32_t ba = base + F_OFF_BH
                            + (warp_col*64 + np*16 + b_row) * SROWB
                            + ks*32 + b_koff;
                uint32_t bh4[4];
                LDSM4(bh4, ba);
                #pragma unroll
                for (int sub = 0; sub < 2; sub++) {
                    #pragma unroll
                    for (int mt = 0; mt < 2; mt++) {
                        MMA_F16(acc[mt][2*np+sub], ah[mt], bh4[2*sub], bh4[2*sub+1]);
                        MMA_F16(acc[mt][2*np+sub], al[mt], bh4[2*sub], bh4[2*sub+1]);
                    }
                }
            }
        }
        __syncthreads();
        if (kc + 2 < nk) issue(kc + 2);
    }

    #pragma unroll
    for (int mt = 0; mt < 2; mt++) {
        const int r0 = m0 + warp_row*32 + mt*16 + lr;
        #pragma unroll
        for (int nt = 0; nt < 8; nt++) {
            const int col = n0 + warp_col*64 + nt*8 + lc*2;
            const float2 bv = *(const float2*)(bias + col);
            *(float2*)(C + (size_t)r0 * Ndim + col) =
                make_float2(acc[mt][nt][0] + bv.x, acc[mt][nt][1] + bv.y);
            *(float2*)(C + (size_t)(r0+8) * Ndim + col) =
                make_float2(acc[mt][nt][2] + bv.x, acc[mt][nt][3] + bv.y);
        }
    }
}

// ---------------------------------------------------------------------------
// Tensor-core flash attention (R8-proven), y epilogue now fp16 hi/lo.
// ---------------------------------------------------------------------------
#define KROWB 272
#define STG_L (64*KROWB)
#define STAGE_A (2*64*KROWB)
#define Q_OFF (2*STAGE_A)
#define ATTN_SMEM (2*STAGE_A + 128*KROWB)

__global__ void __launch_bounds__(256, 1)
attn_kernel(const __nv_bfloat16* __restrict__ qh,
            const __nv_bfloat16* __restrict__ ql,
            const __nv_bfloat16* __restrict__ kh,
            const __nv_bfloat16* __restrict__ kl,
            __half* __restrict__ yh,
            __half* __restrict__ yl)
{
    extern __shared__ char sm[];
    const uint32_t smb = smem_u32(sm);
    const int tid = threadIdx.x;
    const int lane = tid & 31, w = tid >> 5;
    const int lr = lane >> 2, lc = lane & 3;
    const int qt = (int)gridDim.x - 1 - (int)blockIdx.x;   // heavy first
    const int bhid = blockIdx.y;
    const int b = bhid >> 4, h = bhid & 15;

    const char* qbh = (const char*)(qh + ((size_t)b*TSEQ + qt*128)*QSTR + h*LDIM);
    const char* qbl = (const char*)(ql + ((size_t)b*TSEQ + qt*128)*QSTR + h*LDIM);
    const char* kbh = (const char*)(kh + (size_t)b*TSEQ*LDIM);
    const char* kbl = (const char*)(kl + (size_t)b*TSEQ*LDIM);

    uint32_t qfh[8][4], qfl[8][4];
    {
        const int qrow = tid >> 4, qch = tid & 15;
        #pragma unroll
        for (int p = 0; p < 8; p++) {
            int row = p*16 + qrow;
            CP16(smb + Q_OFF + row*KROWB + qch*16, qbh + (size_t)row*QSTR*2 + qch*16);
        }
        CP_COMMIT(); CP_WAIT(0); __syncthreads();
        #pragma unroll
        for (int ks = 0; ks < 8; ks++) {
            uint32_t a = smb + Q_OFF + (w*16 + (lane & 15))*KROWB + ks*32 + (lane & 16);
            LDSM4(qfh[ks], a);
        }
        __syncthreads();
        #pragma unroll
        for (int p = 0; p < 8; p++) {
            int row = p*16 + qrow;
            CP16(smb + Q_OFF + row*KROWB + qch*16, qbl + (size_t)row*QSTR*2 + qch*16);
        }
        CP_COMMIT(); CP_WAIT(0); __syncthreads();
        #pragma unroll
        for (int ks = 0; ks < 8; ks++) {
            uint32_t a = smb + Q_OFF + (w*16 + (lane & 15))*KROWB + ks*32 + (lane & 16);
            LDSM4(qfl[ks], a);
        }
        __syncthreads();
    }

    float yacc[16][4];
    #pragma unroll
    for (int nt = 0; nt < 16; nt++)
        #pragma unroll
        for (int i = 0; i < 4; i++) yacc[nt][i] = 0.f;
    float m0 = -1e30f, m1 = -1e30f, l0 = 0.f, l1 = 0.f;

    const int nkt = 2*qt + 2;
    const int krow = tid >> 4, kch = tid & 15;

    auto issueK = [&](int kt) {
        const uint32_t base = smb + (kt & 1) * STAGE_A;
        #pragma unroll
        for (int p = 0; p < 4; p++) {
            int row = p*16 + krow;
            uint32_t d = base + row*KROWB + kch*16;
            CP16(d,         kbh + (size_t)(kt*64 + row)*256 + kch*16);
            CP16(d + STG_L, kbl + (size_t)(kt*64 + row)*256 + kch*16);
        }
        CP_COMMIT();
    };

    issueK(0);
    if (nkt > 1) issueK(1);

    const float scale = 0.08838834764831845f;
    const int t0g = qt*128 + w*16 + lr, t1g = t0g + 8;
    const int wmax = qt*128 + w*16 + 15;

    for (int kt = 0; kt < nkt; kt++) {
        if (kt + 1 < nkt) CP_WAIT(1); else CP_WAIT(0);
        __syncthreads();
        const uint32_t base = smb + (kt & 1) * STAGE_A;
        const bool diagband = (kt >= 2*qt);
        const bool wskip = diagband && (kt*64 > wmax);

        if (!wskip) {
            float sacc[8][4];
            #pragma unroll
            for (int nt = 0; nt < 8; nt++)
                #pragma unroll
                for (int i = 0; i < 4; i++) sacc[nt][i] = 0.f;

            const int sb_row = (lane & 7) + ((lane & 16) ? 8 : 0);
            const int sb_koff = (lane & 8) ? 16 : 0;
            #pragma unroll
            for (int np = 0; np < 4; np++) {
                if (diagband && kt*64 + np*16 > wmax) break;
                #pragma unroll
                for (int ks = 0; ks < 8; ks++) {
                    uint32_t ba = base + (np*16 + sb_row)*KROWB + ks*32 + sb_koff;
                    uint32_t bh4[4], bl4[4];
                    LDSM4(bh4, ba);
                    LDSM4(bl4, ba + STG_L);
                    #pragma unroll
                    for (int sub = 0; sub < 2; sub++) {
                        MMA_BF16(sacc[2*np+sub], qfh[ks], bh4[2*sub], bh4[2*sub+1]);
                        MMA_BF16(sacc[2*np+sub], qfl[ks], bh4[2*sub], bh4[2*sub+1]);
                        MMA_BF16(sacc[2*np+sub], qfh[ks], bl4[2*sub], bl4[2*sub+1]);
                    }
                }
            }

            #pragma unroll
            for (int nt = 0; nt < 8; nt++)
                #pragma unroll
                for (int i = 0; i < 4; i++) sacc[nt][i] *= scale;
            if (diagband) {
                #pragma unroll
                for (int nt = 0; nt < 8; nt++) {
                    int s0 = kt*64 + nt*8 + 2*lc;
                    if (s0     > t0g) sacc[nt][0] = -1e30f;
                    if (s0 + 1 > t0g) sacc[nt][1] = -1e30f;
                    if (s0     > t1g) sacc[nt][2] = -1e30f;
                    if (s0 + 1 > t1g) sacc[nt][3] = -1e30f;
                }
            }

            float mx0 = -1e30f, mx1 = -1e30f;
            #pragma unroll
            for (int nt = 0; nt < 8; nt++) {
                mx0 = fmaxf(mx0, fmaxf(sacc[nt][0], sacc[nt][1]));
                mx1 = fmaxf(mx1, fmaxf(sacc[nt][2], sacc[nt][3]));
            }
            mx0 = fmaxf(mx0, __shfl_xor_sync(0xffffffffu, mx0, 1));
            mx0 = fmaxf(mx0, __shfl_xor_sync(0xffffffffu, mx0, 2));
            mx1 = fmaxf(mx1, __shfl_xor_sync(0xffffffffu, mx1, 1));
            mx1 = fmaxf(mx1, __shfl_xor_sync(0xffffffffu, mx1, 2));
            float m0n = fmaxf(m0, mx0), m1n = fmaxf(m1, mx1);
            float c0 = __expf(m0 - m0n), c1 = __expf(m1 - m1n);
            float s0sum = 0.f, s1sum = 0.f;
            #pragma unroll
            for (int nt = 0; nt < 8; nt++) {
                float p0 = __expf(sacc[nt][0] - m0n);
                float p1 = __expf(sacc[nt][1] - m0n);
                float p2 = __expf(sacc[nt][2] - m1n);
                float p3 = __expf(sacc[nt][3] - m1n);
                s0sum += p0 + p1; s1sum += p2 + p3;
                sacc[nt][0] = p0; sacc[nt][1] = p1;
                sacc[nt][2] = p2; sacc[nt][3] = p3;
            }
            s0sum += __shfl_xor_sync(0xffffffffu, s0sum, 1);
            s0sum += __shfl_xor_sync(0xffffffffu, s0sum, 2);
            s1sum += __shfl_xor_sync(0xffffffffu, s1sum, 1);
            s1sum += __shfl_xor_sync(0xffffffffu, s1sum, 2);
            l0 = l0*c0 + s0sum; l1 = l1*c1 + s1sum;
            m0 = m0n; m1 = m1n;
            #pragma unroll
            for (int nt = 0; nt < 16; nt++) {
                yacc[nt][0] *= c0; yacc[nt][1] *= c0;
                yacc[nt][2] *= c1; yacc[nt][3] *= c1;
            }

            uint32_t pah[4][4], pal[4][4];
            #pragma unroll
            for (int ks2 = 0; ks2 < 4; ks2++) {
                float p0 = sacc[2*ks2][0], p1 = sacc[2*ks2][1];
                float p2 = sacc[2*ks2][2], p3 = sacc[2*ks2][3];
                float q0 = sacc[2*ks2+1][0], q1 = sacc[2*ks2+1][1];
                float q2 = sacc[2*ks2+1][2], q3 = sacc[2*ks2+1][3];
                pah[ks2][0] = pack2(p0, p1); pah[ks2][1] = pack2(p2, p3);
                pah[ks2][2] = pack2(q0, q1); pah[ks2][3] = pack2(q2, q3);
                pal[ks2][0] = pack2(p0 - bfround(p0), p1 - bfround(p1));
                pal[ks2][1] = pack2(p2 - bfround(p2), p3 - bfround(p3));
                pal[ks2][2] = pack2(q0 - bfround(q0), q1 - bfround(q1));
                pal[ks2][3] = pack2(q2 - bfround(q2), q3 - bfround(q3));
            }

            #pragma unroll
            for (int ks2 = 0; ks2 < 4; ks2++) {
                if (diagband && kt*64 + ks2*16 > wmax) break;
                #pragma unroll
                for (int np = 0; np < 8; np++) {
                    uint32_t va = base + (ks2*16 + (lane & 15))*KROWB
                                + np*32 + (lane & 16);
                    uint32_t vh4[4], vl4[4];
                    LDSM4T(vh4, va);
                    LDSM4T(vl4, va + STG_L);
                    #pragma unroll
                    for (int sub = 0; sub < 2; sub++) {
                        MMA_BF16(yacc[2*np+sub], pah[ks2], vh4[2*sub], vh4[2*sub+1]);
                        MMA_BF16(yacc[2*np+sub], pal[ks2], vh4[2*sub], vh4[2*sub+1]);
                        MMA_BF16(yacc[2*np+sub], pah[ks2], vl4[2*sub], vl4[2*sub+1]);
                    }
                }
            }
        }
        __syncthreads();
        if (kt + 2 < nkt) issueK(kt + 2);
    }

    // Epilogue: normalize, split to fp16 hi/lo (feeds fp16 proj GEMM)
    const float li0 = 1.0f / l0, li1 = 1.0f / l1;
    #pragma unroll
    for (int nt = 0; nt < 16; nt++) {
        float v0 = yacc[nt][0]*li0, v1 = yacc[nt][1]*li0;
        float v2 = yacc[nt][2]*li1, v3 = yacc[nt][3]*li1;
        size_t o0 = ((size_t)b*TSEQ + t0g)*QSTR + h*LDIM + nt*8 + 2*lc;
        size_t o1 = o0 + (size_t)8*QSTR;
        *(uint32_t*)(yh + o0) = pack2h(v0, v1);
        *(uint32_t*)(yl + o0) = pack2h(v0 - hfround(v0), v1 - hfround(v1));
        *(uint32_t*)(yh + o1) = pack2h(v2, v3);
        *(uint32_t*)(yl + o1) = pack2h(v2 - hfround(v2), v3 - hfround(v3));
    }
}

// ---------------------------------------------------------------------------
extern "C" void kernel_launch(void* const* d_in, const int* in_sizes, int n_in,
                              void* d_out, int out_size)
{
    const float* x      = (const float*)d_in[0];
    const float* W_lat  = (const float*)d_in[1];
    const float* b_lat  = (const float*)d_in[2];
    const float* W_d    = (const float*)d_in[3];
    const float* b_d    = (const float*)d_in[4];
    const float* W_proj = (const float*)d_in[5];
    const float* b_proj = (const float*)d_in[6];
    float* out = (float*)d_out;

    __nv_bfloat16 *xh, *xl, *qhp, *qlp, *khp, *klp;
    __half *yhp, *ylp;
    uint32_t *wdh, *wdl, *wph, *wlh, *wll;
    cudaGetSymbolAddress((void**)&xh,  g_xh);
    cudaGetSymbolAddress((void**)&xl,  g_xl);
    cudaGetSymbolAddress((void**)&qhp, g_qh);
    cudaGetSymbolAddress((void**)&qlp, g_ql);
    cudaGetSymbolAddress((void**)&khp, g_kh);
    cudaGetSymbolAddress((void**)&klp, g_kl);
    cudaGetSymbolAddress((void**)&yhp, g_yh);
    cudaGetSymbolAddress((void**)&ylp, g_yl);
    cudaGetSymbolAddress((void**)&wdh, g_wdh);
    cudaGetSymbolAddress((void**)&wdl, g_wdl);
    cudaGetSymbolAddress((void**)&wph, g_wph);
    cudaGetSymbolAddress((void**)&wlh, g_wlh);
    cudaGetSymbolAddress((void**)&wll, g_wll);

    cudaFuncSetAttribute((const void*)gemm_bf16x3,
                         cudaFuncAttributeMaxDynamicSharedMemorySize, GEMM_SMEM);
    cudaFuncSetAttribute((const void*)gemm_f16x2,
                         cudaFuncAttributeMaxDynamicSharedMemorySize, GEMM_SMEM_F16);
    cudaFuncSetAttribute((const void*)attn_kernel,
                         cudaFuncAttributeMaxDynamicSharedMemorySize, ATTN_SMEM);

    dim3 tb(32, 8);
    // 0) split x
    split_rows<<<(MROWS*CEMB/4 + 255)/256, 256>>>(x, xh, xl, MROWS*CEMB);
    // 1) pack W_d (bf16 pairs)
    split_pack_t<<<dim3(CEMB/32, QSTR/32), tb>>>(W_d,   wdh, wdl, CEMB, QSTR);
    // 2) pack W_lat (bf16 pairs)
    split_pack_t<<<dim3(CEMB/32, LDIM/32), tb>>>(W_lat, wlh, wll, CEMB, LDIM);
    // 3) q = x@W_d + b_d fused with k = x@W_lat + b_lat   <-- ncu-profiled slot
    gemm_bf16x3<<<dim3(QSTR/128 + 1, MROWS/128), 256, GEMM_SMEM>>>(
        xh, xl, wdh, wdl, b_d, qhp, qlp, QSTR, CEMB,
        wlh, wll, b_lat, khp, klp, LDIM);
    // 4) pack W_proj (fp16 hi only)
    split_pack_h<<<dim3(QSTR/32, CEMB/32), tb>>>(W_proj, wph, QSTR, CEMB);
    // 5) attention (bf16x3), writes fp16-split y
    attn_kernel<<<dim3(TSEQ/128, BATCH*NHEAD), 256, ATTN_SMEM>>>(
        qhp, qlp, khp, klp, yhp, ylp);
    // 6) out = y @ W_proj + b_proj  (fp16 2-mma, fp32 out)
    gemm_f16x2<<<dim3(CEMB/128, MROWS/128), 256, GEMM_SMEM_F16>>>(
        yhp, ylp, wph, b_proj, out, CEMB, CEMB);
}

// round 10
// speedup vs baseline: 1.2662x; 1.0625x over previous
#include <cuda_runtime.h>
#include <cuda_bf16.h>
#include <cuda_fp16.h>
#include <cstdint>

#define BATCH 2
#define TSEQ 2048
#define CEMB 2048
#define NHEAD 16
#define LDIM 128
#define MROWS (BATCH*TSEQ)
#define QSTR (NHEAD*LDIM)   // 2048

// ---------------------------------------------------------------------------
// Scratch (__device__ globals: allocation-free rule). All fp16 now.
// ---------------------------------------------------------------------------
__device__ __half g_xh[MROWS*CEMB], g_xl[MROWS*CEMB];   // x split
__device__ __half g_qh[MROWS*QSTR], g_ql[MROWS*QSTR];   // q split
__device__ __half g_kh[MROWS*LDIM], g_kl[MROWS*LDIM];   // k split
__device__ __half g_yh[MROWS*QSTR], g_yl[MROWS*QSTR];   // y split
__device__ uint32_t g_wdh[QSTR*(CEMB/2)];               // W_d    fp16 HI pairs
__device__ uint32_t g_wlh[LDIM*(CEMB/2)], g_wll[LDIM*(CEMB/2)];  // W_lat hi/lo
__device__ uint32_t g_wph[CEMB*(QSTR/2)];               // W_proj fp16 HI pairs

// ---------------------------------------------------------------------------
// Helpers
// ---------------------------------------------------------------------------
__device__ __forceinline__ uint32_t smem_u32(const void* p){
    uint32_t a;
    asm("{ .reg .u64 t; cvta.to.shared.u64 t, %1; cvt.u32.u64 %0, t; }"
        : "=r"(a) : "l"(p));
    return a;
}
__device__ __forceinline__ float hfround(float x){
    return __half2float(__float2half_rn(x));
}
__device__ __forceinline__ uint32_t pack2h(float lo, float hi){
    uint32_t r;
    asm("cvt.rn.f16x2.f32 %0, %1, %2;" : "=r"(r) : "f"(hi), "f"(lo));
    return r;
}

#define CP16(dst_u32, src_ptr) \
    asm volatile("cp.async.cg.shared.global [%0], [%1], 16;" \
                 :: "r"(dst_u32), "l"(src_ptr) : "memory")
#define CP_COMMIT() asm volatile("cp.async.commit_group;" ::: "memory")
#define CP_WAIT(n)  asm volatile("cp.async.wait_group %0;" :: "n"(n) : "memory")

#define LDSM4(R, ADDR)                                                        \
    asm volatile("ldmatrix.sync.aligned.m8n8.x4.shared.b16 {%0,%1,%2,%3}, [%4];" \
        : "=r"((R)[0]), "=r"((R)[1]), "=r"((R)[2]), "=r"((R)[3]) : "r"(ADDR))
#define LDSM4T(R, ADDR)                                                       \
    asm volatile("ldmatrix.sync.aligned.m8n8.x4.trans.shared.b16 {%0,%1,%2,%3}, [%4];" \
        : "=r"((R)[0]), "=r"((R)[1]), "=r"((R)[2]), "=r"((R)[3]) : "r"(ADDR))

#define MMA_F16(acc, a, b0, b1)                                               \
    asm volatile(                                                             \
        "mma.sync.aligned.m16n8k16.row.col.f32.f16.f16.f32 "                  \
        "{%0,%1,%2,%3}, {%4,%5,%6,%7}, {%8,%9}, {%0,%1,%2,%3};"               \
        : "+f"((acc)[0]), "+f"((acc)[1]), "+f"((acc)[2]), "+f"((acc)[3])      \
        : "r"((a)[0]), "r"((a)[1]), "r"((a)[2]), "r"((a)[3]),                 \
          "r"(b0), "r"(b1))

// ---------------------------------------------------------------------------
// Split fp32 -> (hi, lo) fp16
// ---------------------------------------------------------------------------
__global__ void split_rows(const float* __restrict__ src,
                           __half* __restrict__ hi,
                           __half* __restrict__ lo, int n)
{
    int i = (blockIdx.x * 256 + threadIdx.x) * 4;
    if (i >= n) return;
    float4 v = *(const float4*)(src + i);
    *(uint32_t*)(hi + i)     = pack2h(v.x, v.y);
    *(uint32_t*)(hi + i + 2) = pack2h(v.z, v.w);
    *(uint32_t*)(lo + i)     = pack2h(v.x - hfround(v.x), v.y - hfround(v.y));
    *(uint32_t*)(lo + i + 2) = pack2h(v.z - hfround(v.z), v.w - hfround(v.w));
}

// ---------------------------------------------------------------------------
// Transpose-pack fp16 HI only:  W[K][N] -> u32 [N][K/2]
// ---------------------------------------------------------------------------
__global__ void split_pack_h(const float* __restrict__ W,
                             uint32_t* __restrict__ hp, int K, int N)
{
    __shared__ float t[32][33];
    const int k0 = blockIdx.x * 32, n0 = blockIdx.y * 32;
    const int tx = threadIdx.x, ty = threadIdx.y;
    for (int i = ty; i < 32; i += 8)
        t[i][tx] = W[(size_t)(k0 + i) * N + n0 + tx];
    __syncthreads();
    if (tx < 16) {
        for (int i = ty; i < 32; i += 8) {
            float v0 = t[2*tx][i], v1 = t[2*tx+1][i];
            hp[(size_t)(n0 + i) * (K >> 1) + (k0 >> 1) + tx] = pack2h(v0, v1);
        }
    }
}

// ---------------------------------------------------------------------------
// Transpose-pack fp16 hi/lo:  W[K][N] -> hi/lo u32 [N][K/2]  (latent weight)
// ---------------------------------------------------------------------------
__global__ void split_pack_th(const float* __restrict__ W,
                              uint32_t* __restrict__ hp,
                              uint32_t* __restrict__ lp, int K, int N)
{
    __shared__ float t[32][33];
    const int k0 = blockIdx.x * 32, n0 = blockIdx.y * 32;
    const int tx = threadIdx.x, ty = threadIdx.y;
    for (int i = ty; i < 32; i += 8)
        t[i][tx] = W[(size_t)(k0 + i) * N + n0 + tx];
    __syncthreads();
    if (tx < 16) {
        for (int i = ty; i < 32; i += 8) {
            float v0 = t[2*tx][i], v1 = t[2*tx+1][i];
            size_t o = (size_t)(n0 + i) * (K >> 1) + (k0 >> 1) + tx;
            hp[o] = pack2h(v0, v1);
            lp[o] = pack2h(v0 - hfround(v0), v1 - hfround(v1));
        }
    }
}

// ---------------------------------------------------------------------------
// Fused q/k GEMM (fp16):  q = x@W_d (2-term), k latent column = x@W_lat
// (3-term: the k error enters both scores and values; keep it near-exact).
// A: fp16 hi/lo [M][K]; B: u32 [N][K/2] fp16 pairs.
// ---------------------------------------------------------------------------
#define SROWB 80
#define REGB  (128*SROWB)
#define OFF_AH 0
#define OFF_AL REGB
#define OFF_BH (2*REGB)
#define OFF_BL (3*REGB)
#define STAGE  (4*REGB)
#define GEMM_SMEM (2*STAGE)

__global__ void __launch_bounds__(256, 2)
gemm_f16qk(const __half* __restrict__ Ah,
           const __half* __restrict__ Al,
           const uint32_t* __restrict__ Bh,
           const float* __restrict__ bias,
           __half* __restrict__ Ch,
           __half* __restrict__ Cl,
           int Ndim, int Kdim,
           const uint32_t* __restrict__ B2h,
           const uint32_t* __restrict__ B2l,
           const float* __restrict__ bias2,
           __half* __restrict__ C2h,
           __half* __restrict__ C2l,
           int N2)
{
    extern __shared__ char sm[];
    const uint32_t smb = smem_u32(sm);
    const int tid = threadIdx.x;
    const int lane = tid & 31, wid = tid >> 5;
    const int warp_row = wid & 3, warp_col = wid >> 2;
    const int m0 = blockIdx.y << 7;
    const int lr = lane >> 2, lc = lane & 3;
    const int KH = Kdim >> 1;

    const uint32_t* pBh = Bh;  const uint32_t* pBl = nullptr;
    const float* pbias = bias;
    __half* pCh = Ch;          __half* pCl = Cl;
    int Nd = Ndim;
    int n0 = blockIdx.x << 7;
    const bool lat3 = (n0 >= Ndim);     // latent column -> 3-term precision
    if (lat3) {
        pBh = B2h; pBl = B2l; pbias = bias2; pCh = C2h; pCl = C2l;
        Nd = N2; n0 = 0;
    }

    float acc[2][8][4];
    #pragma unroll
    for (int mt = 0; mt < 2; mt++)
        #pragma unroll
        for (int nt = 0; nt < 8; nt++)
            #pragma unroll
            for (int i = 0; i < 4; i++) acc[mt][nt][i] = 0.f;

    const int crow = tid >> 2, cch = tid & 3;
    const int nk = Kdim >> 5;

    auto issue = [&](int kc) {
        const uint32_t base = smb + (kc & 1) * STAGE;
        const int k0 = kc << 5, kp0 = kc << 4;
        #pragma unroll
        for (int p = 0; p < 2; p++) {
            int row = p * 64 + crow;
            uint32_t d = base + row * SROWB + cch * 16;
            CP16(d + OFF_AH, Ah + (size_t)(m0 + row) * Kdim + k0 + cch * 8);
            CP16(d + OFF_AL, Al + (size_t)(m0 + row) * Kdim + k0 + cch * 8);
            CP16(d + OFF_BH, pBh + (size_t)(n0 + row) * KH + kp0 + cch * 4);
            if (lat3)
                CP16(d + OFF_BL, pBl + (size_t)(n0 + row) * KH + kp0 + cch * 4);
        }
        CP_COMMIT();
    };

    issue(0);
    if (nk > 1) issue(1);

    const int a_row = lane & 15, a_koff = lane & 16;
    const int b_row = (lane & 7) + ((lane & 16) ? 8 : 0);
    const int b_koff = (lane & 8) ? 16 : 0;

    for (int kc = 0; kc < nk; kc++) {
        if (kc + 1 < nk) CP_WAIT(1); else CP_WAIT(0);
        __syncthreads();
        const uint32_t base = smb + (kc & 1) * STAGE;

        #pragma unroll
        for (int ks = 0; ks < 2; ks++) {
            uint32_t ah[2][4], al[2][4];
            #pragma unroll
            for (int mt = 0; mt < 2; mt++) {
                uint32_t aa = base + OFF_AH
                            + (warp_row*32 + mt*16 + a_row) * SROWB
                            + ks*32 + a_koff;
                LDSM4(ah[mt], aa);
                LDSM4(al[mt], aa + (OFF_AL - OFF_AH));
            }
            #pragma unroll
            for (int np = 0; np < 4; np++) {
                uint32_t ba = base + OFF_BH
                            + (warp_col*64 + np*16 + b_row) * SROWB
                            + ks*32 + b_koff;
                uint32_t bh4[4], bl4[4];
                LDSM4(bh4, ba);
                if (lat3) LDSM4(bl4, ba + (OFF_BL - OFF_BH));
                #pragma unroll
                for (int sub = 0; sub < 2; sub++) {
                    #pragma unroll
                    for (int mt = 0; mt < 2; mt++) {
                        MMA_F16(acc[mt][2*np+sub], ah[mt], bh4[2*sub], bh4[2*sub+1]);
                        MMA_F16(acc[mt][2*np+sub], al[mt], bh4[2*sub], bh4[2*sub+1]);
                        if (lat3)
                            MMA_F16(acc[mt][2*np+sub], ah[mt], bl4[2*sub], bl4[2*sub+1]);
                    }
                }
            }
        }
        __syncthreads();
        if (kc + 2 < nk) issue(kc + 2);
    }

    #pragma unroll
    for (int mt = 0; mt < 2; mt++) {
        const int r0 = m0 + warp_row*32 + mt*16 + lr;
        #pragma unroll
        for (int nt = 0; nt < 8; nt++) {
            const int col = n0 + warp_col*64 + nt*8 + lc*2;
            const float2 bv = *(const float2*)(pbias + col);
            float v0 = acc[mt][nt][0] + bv.x, v1 = acc[mt][nt][1] + bv.y;
            float v2 = acc[mt][nt][2] + bv.x, v3 = acc[mt][nt][3] + bv.y;
            *(uint32_t*)(pCh + (size_t)r0 * Nd + col) = pack2h(v0, v1);
            *(uint32_t*)(pCl + (size_t)r0 * Nd + col) =
                pack2h(v0 - hfround(v0), v1 - hfround(v1));
            *(uint32_t*)(pCh + (size_t)(r0+8) * Nd + col) = pack2h(v2, v3);
            *(uint32_t*)(pCl + (size_t)(r0+8) * Nd + col) =
                pack2h(v2 - hfround(v2), v3 - hfround(v3));
        }
    }
}

// ---------------------------------------------------------------------------
// fp16 2-mma proj GEMM (unchanged from R9):  out = (yh+yl) @ Wp_hi + bias
// ---------------------------------------------------------------------------
#define F_OFF_AH 0
#define F_OFF_AL REGB
#define F_OFF_BH (2*REGB)
#define F_STAGE  (3*REGB)
#define GEMM_SMEM_F16 (2*F_STAGE)

__global__ void __launch_bounds__(256, 2)
gemm_f16x2(const __half* __restrict__ Ah,
           const __half* __restrict__ Al,
           const uint32_t* __restrict__ Bh,
           const float* __restrict__ bias,
           float* __restrict__ C,
           int Ndim, int Kdim)
{
    extern __shared__ char sm[];
    const uint32_t smb = smem_u32(sm);
    const int tid = threadIdx.x;
    const int lane = tid & 31, wid = tid >> 5;
    const int warp_row = wid & 3, warp_col = wid >> 2;
    const int m0 = blockIdx.y << 7, n0 = blockIdx.x << 7;
    const int lr = lane >> 2, lc = lane & 3;
    const int KH = Kdim >> 1;

    float acc[2][8][4];
    #pragma unroll
    for (int mt = 0; mt < 2; mt++)
        #pragma unroll
        for (int nt = 0; nt < 8; nt++)
            #pragma unroll
            for (int i = 0; i < 4; i++) acc[mt][nt][i] = 0.f;

    const int crow = tid >> 2, cch = tid & 3;
    const int nk = Kdim >> 5;

    auto issue = [&](int kc) {
        const uint32_t base = smb + (kc & 1) * F_STAGE;
        const int k0 = kc << 5, kp0 = kc << 4;
        #pragma unroll
        for (int p = 0; p < 2; p++) {
            int row = p * 64 + crow;
            uint32_t d = base + row * SROWB + cch * 16;
            CP16(d + F_OFF_AH, Ah + (size_t)(m0 + row) * Kdim + k0 + cch * 8);
            CP16(d + F_OFF_AL, Al + (size_t)(m0 + row) * Kdim + k0 + cch * 8);
            CP16(d + F_OFF_BH, Bh + (size_t)(n0 + row) * KH + kp0 + cch * 4);
        }
        CP_COMMIT();
    };

    issue(0);
    if (nk > 1) issue(1);

    const int a_row = lane & 15, a_koff = lane & 16;
    const int b_row = (lane & 7) + ((lane & 16) ? 8 : 0);
    const int b_koff = (lane & 8) ? 16 : 0;

    for (int kc = 0; kc < nk; kc++) {
        if (kc + 1 < nk) CP_WAIT(1); else CP_WAIT(0);
        __syncthreads();
        const uint32_t base = smb + (kc & 1) * F_STAGE;

        #pragma unroll
        for (int ks = 0; ks < 2; ks++) {
            uint32_t ah[2][4], al[2][4];
            #pragma unroll
            for (int mt = 0; mt < 2; mt++) {
                uint32_t aa = base + F_OFF_AH
                            + (warp_row*32 + mt*16 + a_row) * SROWB
                            + ks*32 + a_koff;
                LDSM4(ah[mt], aa);
                LDSM4(al[mt], aa + (F_OFF_AL - F_OFF_AH));
            }
            #pragma unroll
            for (int np = 0; np < 4; np++) {
                uint32_t ba = base + F_OFF_BH
                            + (warp_col*64 + np*16 + b_row) * SROWB
                            + ks*32 + b_koff;
                uint32_t bh4[4];
                LDSM4(bh4, ba);
                #pragma unroll
                for (int sub = 0; sub < 2; sub++) {
                    #pragma unroll
                    for (int mt = 0; mt < 2; mt++) {
                        MMA_F16(acc[mt][2*np+sub], ah[mt], bh4[2*sub], bh4[2*sub+1]);
                        MMA_F16(acc[mt][2*np+sub], al[mt], bh4[2*sub], bh4[2*sub+1]);
                    }
                }
            }
        }
        __syncthreads();
        if (kc + 2 < nk) issue(kc + 2);
    }

    #pragma unroll
    for (int mt = 0; mt < 2; mt++) {
        const int r0 = m0 + warp_row*32 + mt*16 + lr;
        #pragma unroll
        for (int nt = 0; nt < 8; nt++) {
            const int col = n0 + warp_col*64 + nt*8 + lc*2;
            const float2 bv = *(const float2*)(bias + col);
            *(float2*)(C + (size_t)r0 * Ndim + col) =
                make_float2(acc[mt][nt][0] + bv.x, acc[mt][nt][1] + bv.y);
            *(float2*)(C + (size_t)(r0+8) * Ndim + col) =
                make_float2(acc[mt][nt][2] + bv.x, acc[mt][nt][3] + bv.y);
        }
    }
}

// ---------------------------------------------------------------------------
// Tensor-core flash attention (fp16): S-pass 3-term (near-exact),
// Y-pass 2-term (P hi/lo vs K hi; error linear in out).
// ---------------------------------------------------------------------------
#define KROWB 272
#define STG_L (64*KROWB)
#define STAGE_A (2*64*KROWB)
#define Q_OFF (2*STAGE_A)
#define ATTN_SMEM (2*STAGE_A + 128*KROWB)

__global__ void __launch_bounds__(256, 1)
attn_kernel(const __half* __restrict__ qh,
            const __half* __restrict__ ql,
            const __half* __restrict__ kh,
            const __half* __restrict__ kl,
            __half* __restrict__ yh,
            __half* __restrict__ yl)
{
    extern __shared__ char sm[];
    const uint32_t smb = smem_u32(sm);
    const int tid = threadIdx.x;
    const int lane = tid & 31, w = tid >> 5;
    const int lr = lane >> 2, lc = lane & 3;
    const int qt = (int)gridDim.x - 1 - (int)blockIdx.x;   // heavy first
    const int bhid = blockIdx.y;
    const int b = bhid >> 4, h = bhid & 15;

    const char* qbh = (const char*)(qh + ((size_t)b*TSEQ + qt*128)*QSTR + h*LDIM);
    const char* qbl = (const char*)(ql + ((size_t)b*TSEQ + qt*128)*QSTR + h*LDIM);
    const char* kbh = (const char*)(kh + (size_t)b*TSEQ*LDIM);
    const char* kbl = (const char*)(kl + (size_t)b*TSEQ*LDIM);

    uint32_t qfh[8][4], qfl[8][4];
    {
        const int qrow = tid >> 4, qch = tid & 15;
        #pragma unroll
        for (int p = 0; p < 8; p++) {
            int row = p*16 + qrow;
            CP16(smb + Q_OFF + row*KROWB + qch*16, qbh + (size_t)row*QSTR*2 + qch*16);
        }
        CP_COMMIT(); CP_WAIT(0); __syncthreads();
        #pragma unroll
        for (int ks = 0; ks < 8; ks++) {
            uint32_t a = smb + Q_OFF + (w*16 + (lane & 15))*KROWB + ks*32 + (lane & 16);
            LDSM4(qfh[ks], a);
        }
        __syncthreads();
        #pragma unroll
        for (int p = 0; p < 8; p++) {
            int row = p*16 + qrow;
            CP16(smb + Q_OFF + row*KROWB + qch*16, qbl + (size_t)row*QSTR*2 + qch*16);
        }
        CP_COMMIT(); CP_WAIT(0); __syncthreads();
        #pragma unroll
        for (int ks = 0; ks < 8; ks++) {
            uint32_t a = smb + Q_OFF + (w*16 + (lane & 15))*KROWB + ks*32 + (lane & 16);
            LDSM4(qfl[ks], a);
        }
        __syncthreads();
    }

    float yacc[16][4];
    #pragma unroll
    for (int nt = 0; nt < 16; nt++)
        #pragma unroll
        for (int i = 0; i < 4; i++) yacc[nt][i] = 0.f;
    float m0 = -1e30f, m1 = -1e30f, l0 = 0.f, l1 = 0.f;

    const int nkt = 2*qt + 2;
    const int krow = tid >> 4, kch = tid & 15;

    auto issueK = [&](int kt) {
        const uint32_t base = smb + (kt & 1) * STAGE_A;
        #pragma unroll
        for (int p = 0; p < 4; p++) {
            int row = p*16 + krow;
            uint32_t d = base + row*KROWB + kch*16;
            CP16(d,         kbh + (size_t)(kt*64 + row)*256 + kch*16);
            CP16(d + STG_L, kbl + (size_t)(kt*64 + row)*256 + kch*16);
        }
        CP_COMMIT();
    };

    issueK(0);
    if (nkt > 1) issueK(1);

    const float scale = 0.08838834764831845f;
    const int t0g = qt*128 + w*16 + lr, t1g = t0g + 8;
    const int wmax = qt*128 + w*16 + 15;

    for (int kt = 0; kt < nkt; kt++) {
        if (kt + 1 < nkt) CP_WAIT(1); else CP_WAIT(0);
        __syncthreads();
        const uint32_t base = smb + (kt & 1) * STAGE_A;
        const bool diagband = (kt >= 2*qt);
        const bool wskip = diagband && (kt*64 > wmax);

        if (!wskip) {
            float sacc[8][4];
            #pragma unroll
            for (int nt = 0; nt < 8; nt++)
                #pragma unroll
                for (int i = 0; i < 4; i++) sacc[nt][i] = 0.f;

            const int sb_row = (lane & 7) + ((lane & 16) ? 8 : 0);
            const int sb_koff = (lane & 8) ? 16 : 0;
            #pragma unroll
            for (int np = 0; np < 4; np++) {
                if (diagband && kt*64 + np*16 > wmax) break;
                #pragma unroll
                for (int ks = 0; ks < 8; ks++) {
                    uint32_t ba = base + (np*16 + sb_row)*KROWB + ks*32 + sb_koff;
                    uint32_t bh4[4], bl4[4];
                    LDSM4(bh4, ba);
                    LDSM4(bl4, ba + STG_L);
                    #pragma unroll
                    for (int sub = 0; sub < 2; sub++) {
                        MMA_F16(sacc[2*np+sub], qfh[ks], bh4[2*sub], bh4[2*sub+1]);
                        MMA_F16(sacc[2*np+sub], qfl[ks], bh4[2*sub], bh4[2*sub+1]);
                        MMA_F16(sacc[2*np+sub], qfh[ks], bl4[2*sub], bl4[2*sub+1]);
                    }
                }
            }

            #pragma unroll
            for (int nt = 0; nt < 8; nt++)
                #pragma unroll
                for (int i = 0; i < 4; i++) sacc[nt][i] *= scale;
            if (diagband) {
                #pragma unroll
                for (int nt = 0; nt < 8; nt++) {
                    int s0 = kt*64 + nt*8 + 2*lc;
                    if (s0     > t0g) sacc[nt][0] = -1e30f;
                    if (s0 + 1 > t0g) sacc[nt][1] = -1e30f;
                    if (s0     > t1g) sacc[nt][2] = -1e30f;
                    if (s0 + 1 > t1g) sacc[nt][3] = -1e30f;
                }
            }

            float mx0 = -1e30f, mx1 = -1e30f;
            #pragma unroll
            for (int nt = 0; nt < 8; nt++) {
                mx0 = fmaxf(mx0, fmaxf(sacc[nt][0], sacc[nt][1]));
                mx1 = fmaxf(mx1, fmaxf(sacc[nt][2], sacc[nt][3]));
            }
            mx0 = fmaxf(mx0, __shfl_xor_sync(0xffffffffu, mx0, 1));
            mx0 = fmaxf(mx0, __shfl_xor_sync(0xffffffffu, mx0, 2));
            mx1 = fmaxf(mx1, __shfl_xor_sync(0xffffffffu, mx1, 1));
            mx1 = fmaxf(mx1, __shfl_xor_sync(0xffffffffu, mx1, 2));
            float m0n = fmaxf(m0, mx0), m1n = fmaxf(m1, mx1);
            float c0 = __expf(m0 - m0n), c1 = __expf(m1 - m1n);
            float s0sum = 0.f, s1sum = 0.f;
            #pragma unroll
            for (int nt = 0; nt < 8; nt++) {
                float p0 = __expf(sacc[nt][0] - m0n);
                float p1 = __expf(sacc[nt][1] - m0n);
                float p2 = __expf(sacc[nt][2] - m1n);
                float p3 = __expf(sacc[nt][3] - m1n);
                s0sum += p0 + p1; s1sum += p2 + p3;
                sacc[nt][0] = p0; sacc[nt][1] = p1;
                sacc[nt][2] = p2; sacc[nt][3] = p3;
            }
            s0sum += __shfl_xor_sync(0xffffffffu, s0sum, 1);
            s0sum += __shfl_xor_sync(0xffffffffu, s0sum, 2);
            s1sum += __shfl_xor_sync(0xffffffffu, s1sum, 1);
            s1sum += __shfl_xor_sync(0xffffffffu, s1sum, 2);
            l0 = l0*c0 + s0sum; l1 = l1*c1 + s1sum;
            m0 = m0n; m1 = m1n;
            #pragma unroll
            for (int nt = 0; nt < 16; nt++) {
                yacc[nt][0] *= c0; yacc[nt][1] *= c0;
                yacc[nt][2] *= c1; yacc[nt][3] *= c1;
            }

            // P fragments fp16 hi/lo (P in [0,1] — ideal for fp16)
            uint32_t pah[4][4], pal[4][4];
            #pragma unroll
            for (int ks2 = 0; ks2 < 4; ks2++) {
                float p0 = sacc[2*ks2][0], p1 = sacc[2*ks2][1];
                float p2 = sacc[2*ks2][2], p3 = sacc[2*ks2][3];
                float q0 = sacc[2*ks2+1][0], q1 = sacc[2*ks2+1][1];
                float q2 = sacc[2*ks2+1][2], q3 = sacc[2*ks2+1][3];
                pah[ks2][0] = pack2h(p0, p1); pah[ks2][1] = pack2h(p2, p3);
                pah[ks2][2] = pack2h(q0, q1); pah[ks2][3] = pack2h(q2, q3);
                pal[ks2][0] = pack2h(p0 - hfround(p0), p1 - hfround(p1));
                pal[ks2][1] = pack2h(p2 - hfround(p2), p3 - hfround(p3));
                pal[ks2][2] = pack2h(q0 - hfround(q0), q1 - hfround(q1));
                pal[ks2][3] = pack2h(q2 - hfround(q2), q3 - hfround(q3));
            }

            // Y += P K : 2-term fp16 (K hi only), no K-lo LDSM
            #pragma unroll
            for (int ks2 = 0; ks2 < 4; ks2++) {
                if (diagband && kt*64 + ks2*16 > wmax) break;
                #pragma unroll
                for (int np = 0; np < 8; np++) {
                    uint32_t va = base + (ks2*16 + (lane & 15))*KROWB
                                + np*32 + (lane & 16);
                    uint32_t vh4[4];
                    LDSM4T(vh4, va);
                    #pragma unroll
                    for (int sub = 0; sub < 2; sub++) {
                        MMA_F16(yacc[2*np+sub], pah[ks2], vh4[2*sub], vh4[2*sub+1]);
                        MMA_F16(yacc[2*np+sub], pal[ks2], vh4[2*sub], vh4[2*sub+1]);
                    }
                }
            }
        }
        __syncthreads();
        if (kt + 2 < nkt) issueK(kt + 2);
    }

    const float li0 = 1.0f / l0, li1 = 1.0f / l1;
    #pragma unroll
    for (int nt = 0; nt < 16; nt++) {
        float v0 = yacc[nt][0]*li0, v1 = yacc[nt][1]*li0;
        float v2 = yacc[nt][2]*li1, v3 = yacc[nt][3]*li1;
        size_t o0 = ((size_t)b*TSEQ + t0g)*QSTR + h*LDIM + nt*8 + 2*lc;
        size_t o1 = o0 + (size_t)8*QSTR;
        *(uint32_t*)(yh + o0) = pack2h(v0, v1);
        *(uint32_t*)(yl + o0) = pack2h(v0 - hfround(v0), v1 - hfround(v1));
        *(uint32_t*)(yh + o1) = pack2h(v2, v3);
        *(uint32_t*)(yl + o1) = pack2h(v2 - hfround(v2), v3 - hfround(v3));
    }
}

// ---------------------------------------------------------------------------
extern "C" void kernel_launch(void* const* d_in, const int* in_sizes, int n_in,
                              void* d_out, int out_size)
{
    const float* x      = (const float*)d_in[0];
    const float* W_lat  = (const float*)d_in[1];
    const float* b_lat  = (const float*)d_in[2];
    const float* W_d    = (const float*)d_in[3];
    const float* b_d    = (const float*)d_in[4];
    const float* W_proj = (const float*)d_in[5];
    const float* b_proj = (const float*)d_in[6];
    float* out = (float*)d_out;

    __half *xh, *xl, *qhp, *qlp, *khp, *klp, *yhp, *ylp;
    uint32_t *wdh, *wph, *wlh, *wll;
    cudaGetSymbolAddress((void**)&xh,  g_xh);
    cudaGetSymbolAddress((void**)&xl,  g_xl);
    cudaGetSymbolAddress((void**)&qhp, g_qh);
    cudaGetSymbolAddress((void**)&qlp, g_ql);
    cudaGetSymbolAddress((void**)&khp, g_kh);
    cudaGetSymbolAddress((void**)&klp, g_kl);
    cudaGetSymbolAddress((void**)&yhp, g_yh);
    cudaGetSymbolAddress((void**)&ylp, g_yl);
    cudaGetSymbolAddress((void**)&wdh, g_wdh);
    cudaGetSymbolAddress((void**)&wph, g_wph);
    cudaGetSymbolAddress((void**)&wlh, g_wlh);
    cudaGetSymbolAddress((void**)&wll, g_wll);

    cudaFuncSetAttribute((const void*)gemm_f16qk,
                         cudaFuncAttributeMaxDynamicSharedMemorySize, GEMM_SMEM);
    cudaFuncSetAttribute((const void*)gemm_f16x2,
                         cudaFuncAttributeMaxDynamicSharedMemorySize, GEMM_SMEM_F16);
    cudaFuncSetAttribute((const void*)attn_kernel,
                         cudaFuncAttributeMaxDynamicSharedMemorySize, ATTN_SMEM);

    dim3 tb(32, 8);
    // 0) split x -> fp16 hi/lo
    split_rows<<<(MROWS*CEMB/4 + 255)/256, 256>>>(x, xh, xl, MROWS*CEMB);
    // 1) pack W_d (fp16 hi only)
    split_pack_h<<<dim3(CEMB/32, QSTR/32), tb>>>(W_d, wdh, CEMB, QSTR);
    // 2) pack W_lat (fp16 hi/lo — k needs 3-term precision)
    split_pack_th<<<dim3(CEMB/32, LDIM/32), tb>>>(W_lat, wlh, wll, CEMB, LDIM);
    // 3) fused q (2-term) + k (3-term) GEMM        <-- ncu-profiled slot
    gemm_f16qk<<<dim3(QSTR/128 + 1, MROWS/128), 256, GEMM_SMEM>>>(
        xh, xl, wdh, b_d, qhp, qlp, QSTR, CEMB,
        wlh, wll, b_lat, khp, klp, LDIM);
    // 4) pack W_proj (fp16 hi only)
    split_pack_h<<<dim3(QSTR/32, CEMB/32), tb>>>(W_proj, wph, QSTR, CEMB);
    // 5) attention: S 3-term, Y 2-term (fp16)
    attn_kernel<<<dim3(TSEQ/128, BATCH*NHEAD), 256, ATTN_SMEM>>>(
        qhp, qlp, khp, klp, yhp, ylp);
    // 6) out = y @ W_proj + b_proj (fp16 2-term, fp32 out)
    gemm_f16x2<<<dim3(CEMB/128, MROWS/128), 256, GEMM_SMEM_F16>>>(
        yhp, ylp, wph, b_proj, out, CEMB, CEMB);
}